// round 8
// baseline (speedup 1.0000x reference)
#include <cuda_runtime.h>
#include <cuda_bf16.h>
#include <math.h>

#define KDIR 6
#define LL 4096
#define DI 128
#define NS 16
#define DTR 4
#define NCH (KDIR * DI)
#define CHK 64
#define LC  (LL / CHK)         // 64

// ---------------- scratch ----------------
__device__ float  g_xx[LL * DI];
__device__ float  g_z [LL * DI];
__device__ float  g_xcT[LL * DI];
__device__ float  g_Bt[KDIR * NS * LL];   // B, [k][n][t] (t contiguous)
__device__ float  g_Ct[KDIR * NS * LL];   // C, [k][n][t]
__device__ float2 g_dd[KDIR * DI * LL];   // (delta, delta*u), [k][d][t]
__device__ float  g_y [KDIR * LL * DI];   // [k][t][d]
__device__ float2 g_chk [NCH * CHK * NS];
__device__ float  g_init[NCH * CHK * NS];

// ---------------- closed-form diagonal permutation ----------------
__device__ __forceinline__ int dg_low(int r) {
    int dg = (int)((sqrtf((float)(8 * r + 1)) - 1.f) * 0.5f);
    while (((dg + 1) * (dg + 2)) >> 1 <= r) dg++;
    while ((dg * (dg + 1)) >> 1 > r) dg--;
    return dg;
}
__device__ __forceinline__ int diag_t(int r) {
    int i, dg;
    if (r < 2080) { dg = dg_low(r); i = r - ((dg * (dg + 1)) >> 1); }
    else {
        int q = 4095 - r;
        int dgm = dg_low(q);
        int p = q - ((dgm * (dgm + 1)) >> 1);
        i = 63 - p;
        dg = 126 - dgm;
    }
    int j = dg - i;
    return (i << 6) | j;
}
__device__ __forceinline__ int rev_idx(int t) {
    int i = t >> 6, c = t & 63, dg = i + c;
    int cum = (dg < 64) ? ((dg * (dg + 1)) >> 1)
                        : 4096 - (((127 - dg) * (128 - dg)) >> 1);
    int lo = dg - 63; if (lo < 0) lo = 0;
    return cum + i - lo;
}
__device__ __forceinline__ int sin_idx(int k, int t) {
    switch (k) {
        case 0: return t;
        case 1: return ((t & 63) << 6) | (t >> 6);
        case 2: return 4095 - t;
        case 3: { int t2 = 4095 - t; return ((t2 & 63) << 6) | (t2 >> 6); }
        case 4: return diag_t(t);
        default: return diag_t(t) ^ 63;
    }
}
__device__ __forceinline__ int iout_idx(int k, int j) {
    switch (k) {
        case 0: return j;
        case 1: return ((j & 63) << 6) | (j >> 6);
        case 2: return 4095 - j;
        case 3: return 4095 - (((j & 63) << 6) | (j >> 6));
        case 4: return rev_idx(j);
        default: return rev_idx(4095 - j);
    }
}

// ---------------- in_proj GEMM ----------------
__global__ void __launch_bounds__(256) k_inproj(const float* __restrict__ x,
                                                const float* __restrict__ W_in) {
    __shared__ float Wsm[128 * 65];
    __shared__ float xsm[32 * 65];
    int tid = threadIdx.x;
    int l0 = blockIdx.x * 32;
    for (int i = tid; i < 32 * 64; i += 256)
        xsm[(i >> 6) * 65 + (i & 63)] = x[(l0 + (i >> 6)) * 64 + (i & 63)];
    int og = tid & 31;
    int lg = tid >> 5;
    for (int ot = 0; ot < 2; ot++) {
        __syncthreads();
        for (int i = tid; i < 128 * 64; i += 256)
            Wsm[(i >> 6) * 65 + (i & 63)] = W_in[(ot * 128 + (i >> 6)) * 64 + (i & 63)];
        __syncthreads();
        float acc[4][4];
        #pragma unroll
        for (int i = 0; i < 4; i++)
            #pragma unroll
            for (int ii = 0; ii < 4; ii++) acc[i][ii] = 0.f;
        for (int c = 0; c < 64; c++) {
            float wv[4], xv[4];
            #pragma unroll
            for (int i = 0; i < 4; i++)  wv[i]  = Wsm[(og + 32 * i) * 65 + c];
            #pragma unroll
            for (int ii = 0; ii < 4; ii++) xv[ii] = xsm[(lg + 8 * ii) * 65 + c];
            #pragma unroll
            for (int i = 0; i < 4; i++)
                #pragma unroll
                for (int ii = 0; ii < 4; ii++)
                    acc[i][ii] = fmaf(wv[i], xv[ii], acc[i][ii]);
        }
        float* dst = (ot == 0) ? g_xx : g_z;
        #pragma unroll
        for (int i = 0; i < 4; i++)
            #pragma unroll
            for (int ii = 0; ii < 4; ii++)
                dst[(l0 + lg + 8 * ii) * 128 + og + 32 * i] = acc[i][ii];
    }
}

// ---------------- depthwise 3x3 conv + bias + SiLU ----------------
__global__ void __launch_bounds__(256) k_conv(const float* __restrict__ conv_w,
                                              const float* __restrict__ conv_b) {
    __shared__ float2 cw[9 * 64];
    __shared__ float2 cb[64];
    int tid = threadIdx.x;
    for (int i = tid; i < 9 * 64; i += 256) {
        int tap = i >> 6, d2 = i & 63;
        cw[i] = make_float2(conv_w[(2 * d2) * 9 + tap], conv_w[(2 * d2 + 1) * 9 + tap]);
    }
    if (tid < 64) cb[tid] = ((const float2*)conv_b)[tid];
    __syncthreads();
    int idx = blockIdx.x * 256 + tid;
    int d2 = idx & 63;
    int l = idx >> 6;
    int h = l >> 6, w = l & 63;
    float2 acc = cb[d2];
    const float2* xx2 = (const float2*)g_xx;
    #pragma unroll
    for (int kh = -1; kh <= 1; kh++) {
        int hh = h + kh;
        if ((unsigned)hh >= 64u) continue;
        #pragma unroll
        for (int kw = -1; kw <= 1; kw++) {
            int wc = w + kw;
            if ((unsigned)wc >= 64u) continue;
            float2 v = xx2[((hh << 6) | wc) * 64 + d2];
            float2 cc = cw[((kh + 1) * 3 + (kw + 1)) * 64 + d2];
            acc.x = fmaf(cc.x, v.x, acc.x);
            acc.y = fmaf(cc.y, v.y, acc.y);
        }
    }
    acc.x = acc.x / (1.f + __expf(-acc.x));
    acc.y = acc.y / (1.f + __expf(-acc.y));
    ((float2*)g_xcT)[l * 64 + d2] = acc;
}

// ---------------- projection + fused delta; B/C transposed output ----------------
__global__ void __launch_bounds__(256) k_proj(const float* __restrict__ x_proj_w,
                                              const float* __restrict__ dt_w,
                                              const float* __restrict__ dt_b) {
    __shared__ float xs[32][129];
    __shared__ float Ps[36 * 128];
    __shared__ float dts[4][32];
    __shared__ float Bsm[16][33];
    __shared__ float Csm[16][33];
    __shared__ int sidx[32];
    int k  = blockIdx.y;
    int t0 = blockIdx.x * 32;
    int tid = threadIdx.x;
    if (tid < 32) sidx[tid] = sin_idx(k, t0 + tid);
    __syncthreads();
    for (int i = tid; i < 36 * 128; i += 256)
        Ps[i] = x_proj_w[k * 36 * 128 + i];
    {
        int lane = tid & 31;
        for (int r = tid >> 5; r < 32; r += 8) {
            int s = sidx[r];
            const float4* src = (const float4*)(g_xcT + s * 128);
            float4 v = src[lane];
            xs[r][lane * 4 + 0] = v.x;
            xs[r][lane * 4 + 1] = v.y;
            xs[r][lane * 4 + 2] = v.z;
            xs[r][lane * 4 + 3] = v.w;
        }
    }
    __syncthreads();
    if (tid < 192) {
        int cg = tid >> 4;
        int tg = tid & 15;
        float acc[3][2] = {{0.f,0.f},{0.f,0.f},{0.f,0.f}};
        for (int dd = 0; dd < 128; dd++) {
            float b0 = xs[tg * 2 + 0][dd];
            float b1 = xs[tg * 2 + 1][dd];
            #pragma unroll
            for (int i = 0; i < 3; i++) {
                float a = Ps[(cg * 3 + i) * 128 + dd];
                acc[i][0] = fmaf(a, b0, acc[i][0]);
                acc[i][1] = fmaf(a, b1, acc[i][1]);
            }
        }
        #pragma unroll
        for (int i = 0; i < 3; i++)
            #pragma unroll
            for (int j = 0; j < 2; j++) {
                int c = cg * 3 + i;
                int tl = tg * 2 + j;
                float v = acc[i][j];
                if (c < 4)       dts[c][tl] = v;
                else if (c < 20) Bsm[c - 4][tl] = v;
                else             Csm[c - 20][tl] = v;
            }
    }
    __syncthreads();
    // B/C write-out, coalesced rows of 32 t
    for (int i = tid; i < 16 * 32; i += 256) {
        int n = i >> 5, t = i & 31;
        g_Bt[(size_t)(k * NS + n) * LL + t0 + t] = Bsm[n][t];
        g_Ct[(size_t)(k * NS + n) * LL + t0 + t] = Csm[n][t];
    }
    // fused delta
    {
        int t = tid & 31;
        int w = tid >> 5;
        #pragma unroll
        for (int it = 0; it < 16; it++) {
            int d = w + 8 * it;
            float acc = dt_b[k * 128 + d];
            #pragma unroll
            for (int r = 0; r < 4; r++)
                acc = fmaf(dt_w[(k * 128 + d) * 4 + r], dts[r][t], acc);
            float delta = (acc > 20.f) ? acc : log1pf(__expf(acc));
            float u = xs[t][d];
            g_dd[(size_t)(k * 128 + d) * LL + t0 + t] = make_float2(delta, delta * u);
        }
    }
}

// ---------------- scan pass 1: per-chunk (xf, aprod), float4 streams ----------------
__global__ void __launch_bounds__(512) k_scan1(const float* __restrict__ A_logs) {
    int tid = threadIdx.x;
    int wl = tid >> 5;
    int ln = tid & 31;
    int k = blockIdx.z, chunk = blockIdx.y, xh = blockIdx.x;
    int dp = xh * 16 + wl;
    int half = ln >> 4, n = ln & 15;
    int d = dp + (half << 6);
    int ch = k * 128 + d;
    int tbeg = chunk * LC;

    const float4* pB4  = (const float4*)(g_Bt + (size_t)(k * NS + n) * LL + tbeg);
    const float4* pDD4 = (const float4*)(g_dd + (size_t)ch * LL + tbeg);
    float cA = -expf(A_logs[ch * 16 + n]) * 1.44269504f;
    float x = 0.f, sdelta = 0.f;
    #pragma unroll 4
    for (int s4 = 0; s4 < LC / 4; s4++) {
        float4 b4 = pB4[s4];
        float4 q0 = pDD4[2 * s4];
        float4 q1 = pDD4[2 * s4 + 1];
        float dA;
        asm("ex2.approx.ftz.f32 %0, %1;" : "=f"(dA) : "f"(q0.x * cA));
        x = fmaf(dA, x, q0.y * b4.x);
        asm("ex2.approx.ftz.f32 %0, %1;" : "=f"(dA) : "f"(q0.z * cA));
        x = fmaf(dA, x, q0.w * b4.y);
        asm("ex2.approx.ftz.f32 %0, %1;" : "=f"(dA) : "f"(q1.x * cA));
        x = fmaf(dA, x, q1.y * b4.z);
        asm("ex2.approx.ftz.f32 %0, %1;" : "=f"(dA) : "f"(q1.z * cA));
        x = fmaf(dA, x, q1.w * b4.w);
        sdelta += (q0.x + q0.z) + (q1.x + q1.z);
    }
    float ap;
    asm("ex2.approx.ftz.f32 %0, %1;" : "=f"(ap) : "f"(sdelta * cA));
    g_chk[((size_t)ch * CHK + chunk) * NS + n] = make_float2(x, ap);
}

// ---------------- scan pass 2: chunk summaries -> initial states ----------------
__global__ void k_scan2() {
    int idx = blockIdx.x * 256 + threadIdx.x;
    if (idx >= NCH * NS) return;
    int ch = idx >> 4;
    int n  = idx & 15;
    float carry = 0.f;
    #pragma unroll 8
    for (int c = 0; c < CHK; c++) {
        size_t off = ((size_t)ch * CHK + c) * NS + n;
        float2 f = g_chk[off];
        g_init[off] = carry;
        carry = fmaf(f.y, carry, f.x);
    }
}

// ---------------- scan pass 3: float4 streams, smem y-assembly ----------------
__global__ void __launch_bounds__(1024) k_scan3(const float* __restrict__ A_logs) {
    __shared__ float xc[32][8][33];
    __shared__ float ytile[8 * 65];
    int tid = threadIdx.x;
    int wl = tid >> 5;
    int ln = tid & 31;
    int k = blockIdx.z, chunk = blockIdx.y, xh = blockIdx.x;
    int dp = xh * 32 + wl;
    int half = ln >> 4, n = ln & 15;
    int d = dp + (half << 6);
    int ch = k * 128 + d;
    int tbeg = chunk * LC;

    const float4* pB4  = (const float4*)(g_Bt + (size_t)(k * NS + n) * LL + tbeg);
    const float4* pC4  = (const float4*)(g_Ct + (size_t)(k * NS + n) * LL + tbeg);
    const float4* pDD4 = (const float4*)(g_dd + (size_t)ch * LL + tbeg);
    float cA = -expf(A_logs[ch * 16 + n]) * 1.44269504f;
    float x = g_init[((size_t)ch * CHK + chunk) * NS + n];

    int rc = ln >> 4;
    int rj = (ln >> 1) & 7;
    int rh = ln & 1;
    int sr = tid >> 6;
    int sc = tid & 63;
    int sd = xh * 32 + (sc & 31) + ((sc >> 5) << 6);
    float* ydst0 = g_y + (size_t)(k * LL + tbeg) * 128 + sd;

    for (int t0 = 0; t0 < LC; t0 += 8) {
        #pragma unroll
        for (int v = 0; v < 2; v++) {
            float4 b4 = pB4[(t0 >> 2) + v];
            float4 c4 = pC4[(t0 >> 2) + v];
            float4 q0 = pDD4[(t0 >> 1) + 2 * v];
            float4 q1 = pDD4[(t0 >> 1) + 2 * v + 1];
            int s = t0 + 4 * v;
            float dA;
            asm("ex2.approx.ftz.f32 %0, %1;" : "=f"(dA) : "f"(q0.x * cA));
            x = fmaf(dA, x, q0.y * b4.x);
            xc[wl][(s + 0) & 7][ln] = x * c4.x;
            asm("ex2.approx.ftz.f32 %0, %1;" : "=f"(dA) : "f"(q0.z * cA));
            x = fmaf(dA, x, q0.w * b4.y);
            xc[wl][(s + 1) & 7][ln] = x * c4.y;
            asm("ex2.approx.ftz.f32 %0, %1;" : "=f"(dA) : "f"(q1.x * cA));
            x = fmaf(dA, x, q1.y * b4.z);
            xc[wl][(s + 2) & 7][ln] = x * c4.z;
            asm("ex2.approx.ftz.f32 %0, %1;" : "=f"(dA) : "f"(q1.z * cA));
            x = fmaf(dA, x, q1.w * b4.w);
            xc[wl][(s + 3) & 7][ln] = x * c4.w;
        }
        __syncwarp();
        float sum = 0.f;
        #pragma unroll
        for (int m = 0; m < 8; m++)
            sum += xc[wl][rj][rc * 16 + rh * 8 + m];
        sum += __shfl_xor_sync(0xffffffffu, sum, 1);
        if (rh == 0) ytile[rj * 65 + rc * 32 + wl] = sum;
        __syncthreads();
        if (tid < 512) ydst0[(size_t)(t0 + sr) * 128] = ytile[sr * 65 + sc];
        __syncthreads();
    }
}

// ---------------- combine: 4 concurrent positions per block ----------------
__global__ void __launch_bounds__(512) k_comb(const float* __restrict__ Ds,
                                              const float* __restrict__ ln_g,
                                              const float* __restrict__ ln_b,
                                              const float* __restrict__ W_out,
                                              float* __restrict__ out) {
    __shared__ float Wsm[64 * 129];
    __shared__ float gsm[4][132];
    __shared__ float red[4][8];
    __shared__ float mus[4][2];
    __shared__ int ism[6 * 16];
    int tid = threadIdx.x;
    int g = tid >> 7;
    int gt = tid & 127;
    for (int i = tid; i < 64 * 128; i += 512)
        Wsm[(i >> 7) * 129 + (i & 127)] = W_out[i];
    if (tid < 96) {
        int kk = tid >> 4, jj = tid & 15;
        ism[kk * 16 + jj] = iout_idx(kk, blockIdx.x * 16 + jj);
    }
    int d = gt;
    float dsum = 0.f;
    #pragma unroll
    for (int k = 0; k < 5; k++) dsum += Ds[k * 128 + d];
    float d5 = Ds[5 * 128 + d];
    float gg = ln_g[d], bb = ln_b[d];
    int lane = tid & 31;
    int wg = gt >> 5;
    int oo = (wg << 4) + (lane & 15);
    int hh2 = lane >> 4;
    __syncthreads();

    for (int it = 0; it < 4; it++) {
        int jj = it * 4 + g;
        int j = blockIdx.x * 16 + jj;
        float y = 0.f;
        #pragma unroll
        for (int k = 0; k < 6; k++)
            y += g_y[(size_t)(k * LL + ism[k * 16 + jj]) * 128 + d];
        int fl = ((63 - (j >> 6)) << 6) | (j & 63);
        y += dsum * g_xcT[j * 128 + d] + d5 * g_xcT[fl * 128 + d];
        float s1 = y, s2 = y * y;
        #pragma unroll
        for (int o = 16; o; o >>= 1) {
            s1 += __shfl_xor_sync(0xffffffffu, s1, o);
            s2 += __shfl_xor_sync(0xffffffffu, s2, o);
        }
        if (lane == 0) { red[g][wg] = s1; red[g][4 + wg] = s2; }
        __syncthreads();
        if (gt == 0) {
            float S1 = red[g][0] + red[g][1] + red[g][2] + red[g][3];
            float S2 = red[g][4] + red[g][5] + red[g][6] + red[g][7];
            float mu = S1 * (1.f / 128.f);
            float var = S2 * (1.f / 128.f) - mu * mu;
            mus[g][0] = mu;
            mus[g][1] = rsqrtf(var + 1e-5f);
        }
        __syncthreads();
        float yn = (y - mus[g][0]) * mus[g][1] * gg + bb;
        float z = g_z[j * 128 + d];
        gsm[g][d] = yn * (z / (1.f + __expf(-z)));
        __syncthreads();
        {
            float acc = 0.f;
            int base = hh2 << 6;
            #pragma unroll 8
            for (int dd = 0; dd < 64; dd++) {
                int c = (dd + (hh2 << 4)) & 63;
                acc = fmaf(Wsm[oo * 129 + base + c], gsm[g][base + c], acc);
            }
            acc += __shfl_xor_sync(0xffffffffu, acc, 16);
            if (hh2 == 0) out[j * 64 + oo] = acc;
        }
        __syncthreads();
    }
}

// ---------------- launch ----------------
extern "C" void kernel_launch(void* const* d_in, const int* in_sizes, int n_in,
                              void* d_out, int out_size) {
    const float* x        = (const float*)d_in[0];
    const float* W_in     = (const float*)d_in[1];
    const float* conv_w   = (const float*)d_in[2];
    const float* conv_b   = (const float*)d_in[3];
    const float* x_proj_w = (const float*)d_in[4];
    const float* dt_w     = (const float*)d_in[5];
    const float* dt_b     = (const float*)d_in[6];
    const float* A_logs   = (const float*)d_in[7];
    const float* Ds       = (const float*)d_in[8];
    const float* ln_g     = (const float*)d_in[9];
    const float* ln_b     = (const float*)d_in[10];
    const float* W_out    = (const float*)d_in[11];
    float* out = (float*)d_out;

    k_inproj<<<128, 256>>>(x, W_in);
    k_conv<<<(LL * 64) / 256, 256>>>(conv_w, conv_b);
    {
        dim3 g(LL / 32, KDIR);
        k_proj<<<g, 256>>>(x_proj_w, dt_w, dt_b);
    }
    {
        dim3 g1(4, CHK, KDIR);
        k_scan1<<<g1, 512>>>(A_logs);
        k_scan2<<<48, 256>>>();
        dim3 g3(2, CHK, KDIR);
        k_scan3<<<g3, 1024>>>(A_logs);
    }
    k_comb<<<256, 512>>>(Ds, ln_g, ln_b, W_out, out);
}

// round 9
// speedup vs baseline: 1.8550x; 1.8550x over previous
#include <cuda_runtime.h>
#include <cuda_bf16.h>
#include <math.h>

#define KDIR 6
#define LL 4096
#define DI 128
#define NS 16
#define DTR 4
#define NCH (KDIR * DI)
#define CHK 64
#define LC  (LL / CHK)         // 64

// ---------------- scratch ----------------
__device__ float  g_xx[LL * DI];
__device__ float  g_z [LL * DI];
__device__ float  g_xcT[LL * DI];
__device__ float2 g_BC[KDIR * LL * NS];   // (B,C), [k][t][n] interleaved
__device__ float2 g_dd[KDIR * DI * LL];   // (delta, delta*u), [k][d][t]
__device__ float  g_y [KDIR * LL * DI];   // [k][t][d]
__device__ float2 g_chk [NCH * CHK * NS];
__device__ float  g_init[NCH * CHK * NS];

// ---------------- closed-form diagonal permutation ----------------
__device__ __forceinline__ int dg_low(int r) {
    int dg = (int)((sqrtf((float)(8 * r + 1)) - 1.f) * 0.5f);
    while (((dg + 1) * (dg + 2)) >> 1 <= r) dg++;
    while ((dg * (dg + 1)) >> 1 > r) dg--;
    return dg;
}
__device__ __forceinline__ int diag_t(int r) {
    int i, dg;
    if (r < 2080) { dg = dg_low(r); i = r - ((dg * (dg + 1)) >> 1); }
    else {
        int q = 4095 - r;
        int dgm = dg_low(q);
        int p = q - ((dgm * (dgm + 1)) >> 1);
        i = 63 - p;
        dg = 126 - dgm;
    }
    int j = dg - i;
    return (i << 6) | j;
}
__device__ __forceinline__ int rev_idx(int t) {
    int i = t >> 6, c = t & 63, dg = i + c;
    int cum = (dg < 64) ? ((dg * (dg + 1)) >> 1)
                        : 4096 - (((127 - dg) * (128 - dg)) >> 1);
    int lo = dg - 63; if (lo < 0) lo = 0;
    return cum + i - lo;
}
__device__ __forceinline__ int sin_idx(int k, int t) {
    switch (k) {
        case 0: return t;
        case 1: return ((t & 63) << 6) | (t >> 6);
        case 2: return 4095 - t;
        case 3: { int t2 = 4095 - t; return ((t2 & 63) << 6) | (t2 >> 6); }
        case 4: return diag_t(t);
        default: return diag_t(t) ^ 63;
    }
}
__device__ __forceinline__ int iout_idx(int k, int j) {
    switch (k) {
        case 0: return j;
        case 1: return ((j & 63) << 6) | (j >> 6);
        case 2: return 4095 - j;
        case 3: return 4095 - (((j & 63) << 6) | (j >> 6));
        case 4: return rev_idx(j);
        default: return rev_idx(4095 - j);
    }
}

// ---------------- in_proj GEMM ----------------
__global__ void __launch_bounds__(256) k_inproj(const float* __restrict__ x,
                                                const float* __restrict__ W_in) {
    __shared__ float Wsm[128 * 65];
    __shared__ float xsm[32 * 65];
    int tid = threadIdx.x;
    int l0 = blockIdx.x * 32;
    for (int i = tid; i < 32 * 64; i += 256)
        xsm[(i >> 6) * 65 + (i & 63)] = x[(l0 + (i >> 6)) * 64 + (i & 63)];
    int og = tid & 31;
    int lg = tid >> 5;
    for (int ot = 0; ot < 2; ot++) {
        __syncthreads();
        for (int i = tid; i < 128 * 64; i += 256)
            Wsm[(i >> 6) * 65 + (i & 63)] = W_in[(ot * 128 + (i >> 6)) * 64 + (i & 63)];
        __syncthreads();
        float acc[4][4];
        #pragma unroll
        for (int i = 0; i < 4; i++)
            #pragma unroll
            for (int ii = 0; ii < 4; ii++) acc[i][ii] = 0.f;
        for (int c = 0; c < 64; c++) {
            float wv[4], xv[4];
            #pragma unroll
            for (int i = 0; i < 4; i++)  wv[i]  = Wsm[(og + 32 * i) * 65 + c];
            #pragma unroll
            for (int ii = 0; ii < 4; ii++) xv[ii] = xsm[(lg + 8 * ii) * 65 + c];
            #pragma unroll
            for (int i = 0; i < 4; i++)
                #pragma unroll
                for (int ii = 0; ii < 4; ii++)
                    acc[i][ii] = fmaf(wv[i], xv[ii], acc[i][ii]);
        }
        float* dst = (ot == 0) ? g_xx : g_z;
        #pragma unroll
        for (int i = 0; i < 4; i++)
            #pragma unroll
            for (int ii = 0; ii < 4; ii++)
                dst[(l0 + lg + 8 * ii) * 128 + og + 32 * i] = acc[i][ii];
    }
}

// ---------------- depthwise 3x3 conv + bias + SiLU ----------------
__global__ void __launch_bounds__(256) k_conv(const float* __restrict__ conv_w,
                                              const float* __restrict__ conv_b) {
    __shared__ float2 cw[9 * 64];
    __shared__ float2 cb[64];
    int tid = threadIdx.x;
    for (int i = tid; i < 9 * 64; i += 256) {
        int tap = i >> 6, d2 = i & 63;
        cw[i] = make_float2(conv_w[(2 * d2) * 9 + tap], conv_w[(2 * d2 + 1) * 9 + tap]);
    }
    if (tid < 64) cb[tid] = ((const float2*)conv_b)[tid];
    __syncthreads();
    int idx = blockIdx.x * 256 + tid;
    int d2 = idx & 63;
    int l = idx >> 6;
    int h = l >> 6, w = l & 63;
    float2 acc = cb[d2];
    const float2* xx2 = (const float2*)g_xx;
    #pragma unroll
    for (int kh = -1; kh <= 1; kh++) {
        int hh = h + kh;
        if ((unsigned)hh >= 64u) continue;
        #pragma unroll
        for (int kw = -1; kw <= 1; kw++) {
            int wc = w + kw;
            if ((unsigned)wc >= 64u) continue;
            float2 v = xx2[((hh << 6) | wc) * 64 + d2];
            float2 cc = cw[((kh + 1) * 3 + (kw + 1)) * 64 + d2];
            acc.x = fmaf(cc.x, v.x, acc.x);
            acc.y = fmaf(cc.y, v.y, acc.y);
        }
    }
    acc.x = acc.x / (1.f + __expf(-acc.x));
    acc.y = acc.y / (1.f + __expf(-acc.y));
    ((float2*)g_xcT)[l * 64 + d2] = acc;
}

// ---------------- projection + fused delta (interleaved BC output) ----------------
__global__ void __launch_bounds__(256) k_proj(const float* __restrict__ x_proj_w,
                                              const float* __restrict__ dt_w,
                                              const float* __restrict__ dt_b) {
    __shared__ float xs[32][129];
    __shared__ float Ps[36 * 128];
    __shared__ float dts[4][32];
    __shared__ int sidx[32];
    int k  = blockIdx.y;
    int t0 = blockIdx.x * 32;
    int tid = threadIdx.x;
    if (tid < 32) sidx[tid] = sin_idx(k, t0 + tid);
    __syncthreads();
    for (int i = tid; i < 36 * 128; i += 256)
        Ps[i] = x_proj_w[k * 36 * 128 + i];
    {
        int lane = tid & 31;
        for (int r = tid >> 5; r < 32; r += 8) {
            int s = sidx[r];
            const float4* src = (const float4*)(g_xcT + s * 128);
            float4 v = src[lane];
            xs[r][lane * 4 + 0] = v.x;
            xs[r][lane * 4 + 1] = v.y;
            xs[r][lane * 4 + 2] = v.z;
            xs[r][lane * 4 + 3] = v.w;
        }
    }
    __syncthreads();
    if (tid < 192) {
        int cg = tid >> 4;
        int tg = tid & 15;
        float acc[3][2] = {{0.f,0.f},{0.f,0.f},{0.f,0.f}};
        for (int dd = 0; dd < 128; dd++) {
            float b0 = xs[tg * 2 + 0][dd];
            float b1 = xs[tg * 2 + 1][dd];
            #pragma unroll
            for (int i = 0; i < 3; i++) {
                float a = Ps[(cg * 3 + i) * 128 + dd];
                acc[i][0] = fmaf(a, b0, acc[i][0]);
                acc[i][1] = fmaf(a, b1, acc[i][1]);
            }
        }
        #pragma unroll
        for (int i = 0; i < 3; i++)
            #pragma unroll
            for (int j = 0; j < 2; j++) {
                int c = cg * 3 + i;
                int tl = tg * 2 + j;
                int t = t0 + tl;
                float v = acc[i][j];
                if (c < 4)       dts[c][tl] = v;
                else if (c < 20) g_BC[(size_t)(k * LL + t) * NS + (c - 4)].x = v;
                else             g_BC[(size_t)(k * LL + t) * NS + (c - 20)].y = v;
            }
    }
    __syncthreads();
    {
        int t = tid & 31;
        int w = tid >> 5;
        #pragma unroll
        for (int it = 0; it < 16; it++) {
            int d = w + 8 * it;
            float acc = dt_b[k * 128 + d];
            #pragma unroll
            for (int r = 0; r < 4; r++)
                acc = fmaf(dt_w[(k * 128 + d) * 4 + r], dts[r][t], acc);
            float delta = (acc > 20.f) ? acc : log1pf(__expf(acc));
            float u = xs[t][d];
            g_dd[(size_t)(k * 128 + d) * LL + t0 + t] = make_float2(delta, delta * u);
        }
    }
}

// ---------------- scan pass 1: smem-staged B, float4 dd ----------------
__global__ void __launch_bounds__(512) k_scan1(const float* __restrict__ A_logs) {
    __shared__ float bb[LC * 16];          // 4 KB
    int tid = threadIdx.x;
    int wl = tid >> 5;
    int ln = tid & 31;
    int k = blockIdx.z, chunk = blockIdx.y, xh = blockIdx.x;
    int dp = xh * 16 + wl;
    int half = ln >> 4, n = ln & 15;
    int d = dp + (half << 6);
    int ch = k * 128 + d;
    int tbeg = chunk * LC;

    const float2* srcBC = g_BC + (size_t)(k * LL + tbeg) * NS;
    for (int i = tid; i < LC * 16; i += 512) bb[i] = srcBC[i].x;
    __syncthreads();

    const float4* pDD4 = (const float4*)(g_dd + (size_t)ch * LL + tbeg);
    float cA = -expf(A_logs[ch * 16 + n]) * 1.44269504f;
    float x = 0.f, sdelta = 0.f;
    #pragma unroll 4
    for (int s2 = 0; s2 < LC / 2; s2++) {
        float4 q = pDD4[s2];
        float b0 = bb[(2 * s2) * 16 + n];
        float b1 = bb[(2 * s2 + 1) * 16 + n];
        float dA;
        asm("ex2.approx.ftz.f32 %0, %1;" : "=f"(dA) : "f"(q.x * cA));
        x = fmaf(dA, x, q.y * b0);
        asm("ex2.approx.ftz.f32 %0, %1;" : "=f"(dA) : "f"(q.z * cA));
        x = fmaf(dA, x, q.w * b1);
        sdelta += q.x + q.z;
    }
    float ap;
    asm("ex2.approx.ftz.f32 %0, %1;" : "=f"(ap) : "f"(sdelta * cA));
    g_chk[((size_t)ch * CHK + chunk) * NS + n] = make_float2(x, ap);
}

// ---------------- scan pass 2: chunk summaries -> initial states ----------------
__global__ void k_scan2() {
    int idx = blockIdx.x * 256 + threadIdx.x;
    if (idx >= NCH * NS) return;
    int ch = idx >> 4;
    int n  = idx & 15;
    float carry = 0.f;
    #pragma unroll 8
    for (int c = 0; c < CHK; c++) {
        size_t off = ((size_t)ch * CHK + c) * NS + n;
        float2 f = g_chk[off];
        g_init[off] = carry;
        carry = fmaf(f.y, carry, f.x);
    }
}

// ---------------- scan pass 3: smem-staged BC, float4 dd, smem y-assembly ----------------
__global__ void __launch_bounds__(1024) k_scan3(const float* __restrict__ A_logs) {
    __shared__ float2 bcs[LC * 16];        // 8 KB
    __shared__ float xc[32][8][33];        // 33.8 KB
    __shared__ float ytile[8 * 65];        // 2 KB
    int tid = threadIdx.x;
    int wl = tid >> 5;
    int ln = tid & 31;
    int k = blockIdx.z, chunk = blockIdx.y, xh = blockIdx.x;
    int dp = xh * 32 + wl;
    int half = ln >> 4, n = ln & 15;
    int d = dp + (half << 6);
    int ch = k * 128 + d;
    int tbeg = chunk * LC;

    {
        const float4* src = (const float4*)(g_BC + (size_t)(k * LL + tbeg) * NS);
        if (tid < 512) ((float4*)bcs)[tid] = src[tid];   // 1024 float2 = 512 float4
    }
    __syncthreads();

    const float4* pDD4 = (const float4*)(g_dd + (size_t)ch * LL + tbeg);
    float cA = -expf(A_logs[ch * 16 + n]) * 1.44269504f;
    float x = g_init[((size_t)ch * CHK + chunk) * NS + n];

    int rc = ln >> 4;
    int rj = (ln >> 1) & 7;
    int rh = ln & 1;
    int sr = tid >> 6;
    int sc = tid & 63;
    int sd = xh * 32 + (sc & 31) + ((sc >> 5) << 6);
    float* ydst0 = g_y + (size_t)(k * LL + tbeg) * 128 + sd;

    for (int t0 = 0; t0 < LC; t0 += 8) {
        #pragma unroll
        for (int v = 0; v < 2; v++) {
            float4 q0 = pDD4[(t0 >> 1) + 2 * v];
            float4 q1 = pDD4[(t0 >> 1) + 2 * v + 1];
            int s = t0 + 4 * v;
            float2 bc0 = bcs[(s + 0) * 16 + n];
            float2 bc1 = bcs[(s + 1) * 16 + n];
            float2 bc2 = bcs[(s + 2) * 16 + n];
            float2 bc3 = bcs[(s + 3) * 16 + n];
            float dA;
            asm("ex2.approx.ftz.f32 %0, %1;" : "=f"(dA) : "f"(q0.x * cA));
            x = fmaf(dA, x, q0.y * bc0.x);
            xc[wl][(s + 0) & 7][ln] = x * bc0.y;
            asm("ex2.approx.ftz.f32 %0, %1;" : "=f"(dA) : "f"(q0.z * cA));
            x = fmaf(dA, x, q0.w * bc1.x);
            xc[wl][(s + 1) & 7][ln] = x * bc1.y;
            asm("ex2.approx.ftz.f32 %0, %1;" : "=f"(dA) : "f"(q1.x * cA));
            x = fmaf(dA, x, q1.y * bc2.x);
            xc[wl][(s + 2) & 7][ln] = x * bc2.y;
            asm("ex2.approx.ftz.f32 %0, %1;" : "=f"(dA) : "f"(q1.z * cA));
            x = fmaf(dA, x, q1.w * bc3.x);
            xc[wl][(s + 3) & 7][ln] = x * bc3.y;
        }
        __syncwarp();
        float sum = 0.f;
        #pragma unroll
        for (int m = 0; m < 8; m++)
            sum += xc[wl][rj][rc * 16 + rh * 8 + m];
        sum += __shfl_xor_sync(0xffffffffu, sum, 1);
        if (rh == 0) ytile[rj * 65 + rc * 32 + wl] = sum;
        __syncthreads();
        if (tid < 512) ydst0[(size_t)(t0 + sr) * 128] = ytile[sr * 65 + sc];
        __syncthreads();
    }
}

// ---------------- combine: 4 concurrent positions per block ----------------
__global__ void __launch_bounds__(512) k_comb(const float* __restrict__ Ds,
                                              const float* __restrict__ ln_g,
                                              const float* __restrict__ ln_b,
                                              const float* __restrict__ W_out,
                                              float* __restrict__ out) {
    __shared__ float Wsm[64 * 129];
    __shared__ float gsm[4][132];
    __shared__ float red[4][8];
    __shared__ float mus[4][2];
    __shared__ int ism[6 * 16];
    int tid = threadIdx.x;
    int g = tid >> 7;
    int gt = tid & 127;
    for (int i = tid; i < 64 * 128; i += 512)
        Wsm[(i >> 7) * 129 + (i & 127)] = W_out[i];
    if (tid < 96) {
        int kk = tid >> 4, jj = tid & 15;
        ism[kk * 16 + jj] = iout_idx(kk, blockIdx.x * 16 + jj);
    }
    int d = gt;
    float dsum = 0.f;
    #pragma unroll
    for (int k = 0; k < 5; k++) dsum += Ds[k * 128 + d];
    float d5 = Ds[5 * 128 + d];
    float gg = ln_g[d], bb = ln_b[d];
    int lane = tid & 31;
    int wg = gt >> 5;
    int oo = (wg << 4) + (lane & 15);
    int hh2 = lane >> 4;
    __syncthreads();

    for (int it = 0; it < 4; it++) {
        int jj = it * 4 + g;
        int j = blockIdx.x * 16 + jj;
        float y = 0.f;
        #pragma unroll
        for (int k = 0; k < 6; k++)
            y += g_y[(size_t)(k * LL + ism[k * 16 + jj]) * 128 + d];
        int fl = ((63 - (j >> 6)) << 6) | (j & 63);
        y += dsum * g_xcT[j * 128 + d] + d5 * g_xcT[fl * 128 + d];
        float s1 = y, s2 = y * y;
        #pragma unroll
        for (int o = 16; o; o >>= 1) {
            s1 += __shfl_xor_sync(0xffffffffu, s1, o);
            s2 += __shfl_xor_sync(0xffffffffu, s2, o);
        }
        if (lane == 0) { red[g][wg] = s1; red[g][4 + wg] = s2; }
        __syncthreads();
        if (gt == 0) {
            float S1 = red[g][0] + red[g][1] + red[g][2] + red[g][3];
            float S2 = red[g][4] + red[g][5] + red[g][6] + red[g][7];
            float mu = S1 * (1.f / 128.f);
            float var = S2 * (1.f / 128.f) - mu * mu;
            mus[g][0] = mu;
            mus[g][1] = rsqrtf(var + 1e-5f);
        }
        __syncthreads();
        float yn = (y - mus[g][0]) * mus[g][1] * gg + bb;
        float z = g_z[j * 128 + d];
        gsm[g][d] = yn * (z / (1.f + __expf(-z)));
        __syncthreads();
        {
            float acc = 0.f;
            int base = hh2 << 6;
            #pragma unroll 8
            for (int dd = 0; dd < 64; dd++) {
                int c = (dd + (hh2 << 4)) & 63;
                acc = fmaf(Wsm[oo * 129 + base + c], gsm[g][base + c], acc);
            }
            acc += __shfl_xor_sync(0xffffffffu, acc, 16);
            if (hh2 == 0) out[j * 64 + oo] = acc;
        }
        __syncthreads();
    }
}

// ---------------- launch ----------------
extern "C" void kernel_launch(void* const* d_in, const int* in_sizes, int n_in,
                              void* d_out, int out_size) {
    const float* x        = (const float*)d_in[0];
    const float* W_in     = (const float*)d_in[1];
    const float* conv_w   = (const float*)d_in[2];
    const float* conv_b   = (const float*)d_in[3];
    const float* x_proj_w = (const float*)d_in[4];
    const float* dt_w     = (const float*)d_in[5];
    const float* dt_b     = (const float*)d_in[6];
    const float* A_logs   = (const float*)d_in[7];
    const float* Ds       = (const float*)d_in[8];
    const float* ln_g     = (const float*)d_in[9];
    const float* ln_b     = (const float*)d_in[10];
    const float* W_out    = (const float*)d_in[11];
    float* out = (float*)d_out;

    k_inproj<<<128, 256>>>(x, W_in);
    k_conv<<<(LL * 64) / 256, 256>>>(conv_w, conv_b);
    {
        dim3 g(LL / 32, KDIR);
        k_proj<<<g, 256>>>(x_proj_w, dt_w, dt_b);
    }
    {
        dim3 g1(4, CHK, KDIR);
        k_scan1<<<g1, 512>>>(A_logs);
        k_scan2<<<48, 256>>>();
        dim3 g3(2, CHK, KDIR);
        k_scan3<<<g3, 1024>>>(A_logs);
    }
    k_comb<<<256, 512>>>(Ds, ln_g, ln_b, W_out, out);
}

// round 10
// speedup vs baseline: 1.8581x; 1.0017x over previous
#include <cuda_runtime.h>
#include <cuda_bf16.h>
#include <math.h>

#define KDIR 6
#define LL 4096
#define DI 128
#define NS 16
#define DTR 4
#define NCH (KDIR * DI)
#define CHK 64
#define LC  (LL / CHK)         // 64

// ---------------- scratch ----------------
__device__ float  g_xx[LL * DI];
__device__ float  g_z [LL * DI];
__device__ float  g_xcT[LL * DI];
__device__ float2 g_BC[KDIR * LL * NS];   // (B,C), [k][t][n] interleaved
__device__ float2 g_dd[KDIR * DI * LL];   // (delta, delta*u), [k][d][t]
__device__ float  g_y [KDIR * LL * DI];   // [k][t][d]
__device__ float2 g_chk [NCH * CHK * NS];
__device__ float  g_init[NCH * CHK * NS];

// ---------------- closed-form diagonal permutation ----------------
__device__ __forceinline__ int dg_low(int r) {
    int dg = (int)((sqrtf((float)(8 * r + 1)) - 1.f) * 0.5f);
    while (((dg + 1) * (dg + 2)) >> 1 <= r) dg++;
    while ((dg * (dg + 1)) >> 1 > r) dg--;
    return dg;
}
__device__ __forceinline__ int diag_t(int r) {
    int i, dg;
    if (r < 2080) { dg = dg_low(r); i = r - ((dg * (dg + 1)) >> 1); }
    else {
        int q = 4095 - r;
        int dgm = dg_low(q);
        int p = q - ((dgm * (dgm + 1)) >> 1);
        i = 63 - p;
        dg = 126 - dgm;
    }
    int j = dg - i;
    return (i << 6) | j;
}
__device__ __forceinline__ int rev_idx(int t) {
    int i = t >> 6, c = t & 63, dg = i + c;
    int cum = (dg < 64) ? ((dg * (dg + 1)) >> 1)
                        : 4096 - (((127 - dg) * (128 - dg)) >> 1);
    int lo = dg - 63; if (lo < 0) lo = 0;
    return cum + i - lo;
}
__device__ __forceinline__ int sin_idx(int k, int t) {
    switch (k) {
        case 0: return t;
        case 1: return ((t & 63) << 6) | (t >> 6);
        case 2: return 4095 - t;
        case 3: { int t2 = 4095 - t; return ((t2 & 63) << 6) | (t2 >> 6); }
        case 4: return diag_t(t);
        default: return diag_t(t) ^ 63;
    }
}
__device__ __forceinline__ int iout_idx(int k, int j) {
    switch (k) {
        case 0: return j;
        case 1: return ((j & 63) << 6) | (j >> 6);
        case 2: return 4095 - j;
        case 3: return 4095 - (((j & 63) << 6) | (j >> 6));
        case 4: return rev_idx(j);
        default: return rev_idx(4095 - j);
    }
}

// ---------------- in_proj GEMM ----------------
__global__ void __launch_bounds__(256) k_inproj(const float* __restrict__ x,
                                                const float* __restrict__ W_in) {
    __shared__ float Wsm[128 * 65];
    __shared__ float xsm[32 * 65];
    int tid = threadIdx.x;
    int l0 = blockIdx.x * 32;
    for (int i = tid; i < 32 * 64; i += 256)
        xsm[(i >> 6) * 65 + (i & 63)] = x[(l0 + (i >> 6)) * 64 + (i & 63)];
    int og = tid & 31;
    int lg = tid >> 5;
    for (int ot = 0; ot < 2; ot++) {
        __syncthreads();
        for (int i = tid; i < 128 * 64; i += 256)
            Wsm[(i >> 6) * 65 + (i & 63)] = W_in[(ot * 128 + (i >> 6)) * 64 + (i & 63)];
        __syncthreads();
        float acc[4][4];
        #pragma unroll
        for (int i = 0; i < 4; i++)
            #pragma unroll
            for (int ii = 0; ii < 4; ii++) acc[i][ii] = 0.f;
        for (int c = 0; c < 64; c++) {
            float wv[4], xv[4];
            #pragma unroll
            for (int i = 0; i < 4; i++)  wv[i]  = Wsm[(og + 32 * i) * 65 + c];
            #pragma unroll
            for (int ii = 0; ii < 4; ii++) xv[ii] = xsm[(lg + 8 * ii) * 65 + c];
            #pragma unroll
            for (int i = 0; i < 4; i++)
                #pragma unroll
                for (int ii = 0; ii < 4; ii++)
                    acc[i][ii] = fmaf(wv[i], xv[ii], acc[i][ii]);
        }
        float* dst = (ot == 0) ? g_xx : g_z;
        #pragma unroll
        for (int i = 0; i < 4; i++)
            #pragma unroll
            for (int ii = 0; ii < 4; ii++)
                dst[(l0 + lg + 8 * ii) * 128 + og + 32 * i] = acc[i][ii];
    }
}

// ---------------- depthwise 3x3 conv + bias + SiLU ----------------
__global__ void __launch_bounds__(256) k_conv(const float* __restrict__ conv_w,
                                              const float* __restrict__ conv_b) {
    __shared__ float2 cw[9 * 64];
    __shared__ float2 cb[64];
    int tid = threadIdx.x;
    for (int i = tid; i < 9 * 64; i += 256) {
        int tap = i >> 6, d2 = i & 63;
        cw[i] = make_float2(conv_w[(2 * d2) * 9 + tap], conv_w[(2 * d2 + 1) * 9 + tap]);
    }
    if (tid < 64) cb[tid] = ((const float2*)conv_b)[tid];
    __syncthreads();
    int idx = blockIdx.x * 256 + tid;
    int d2 = idx & 63;
    int l = idx >> 6;
    int h = l >> 6, w = l & 63;
    float2 acc = cb[d2];
    const float2* xx2 = (const float2*)g_xx;
    #pragma unroll
    for (int kh = -1; kh <= 1; kh++) {
        int hh = h + kh;
        if ((unsigned)hh >= 64u) continue;
        #pragma unroll
        for (int kw = -1; kw <= 1; kw++) {
            int wc = w + kw;
            if ((unsigned)wc >= 64u) continue;
            float2 v = xx2[((hh << 6) | wc) * 64 + d2];
            float2 cc = cw[((kh + 1) * 3 + (kw + 1)) * 64 + d2];
            acc.x = fmaf(cc.x, v.x, acc.x);
            acc.y = fmaf(cc.y, v.y, acc.y);
        }
    }
    acc.x = acc.x / (1.f + __expf(-acc.x));
    acc.y = acc.y / (1.f + __expf(-acc.y));
    ((float2*)g_xcT)[l * 64 + d2] = acc;
}

// ---------------- projection + fused delta ----------------
__global__ void __launch_bounds__(256) k_proj(const float* __restrict__ x_proj_w,
                                              const float* __restrict__ dt_w,
                                              const float* __restrict__ dt_b) {
    __shared__ float xs[32][129];
    __shared__ __align__(16) float Ps[36 * 128];
    __shared__ float dts[4][32];
    __shared__ int sidx[32];
    int k  = blockIdx.y;
    int t0 = blockIdx.x * 32;
    int tid = threadIdx.x;
    if (tid < 32) sidx[tid] = sin_idx(k, t0 + tid);
    __syncthreads();
    for (int i = tid; i < 36 * 128; i += 256)
        Ps[i] = x_proj_w[k * 36 * 128 + i];
    {
        int lane = tid & 31;
        for (int r = tid >> 5; r < 32; r += 8) {
            int s = sidx[r];
            const float4* src = (const float4*)(g_xcT + s * 128);
            float4 v = src[lane];
            xs[r][lane * 4 + 0] = v.x;
            xs[r][lane * 4 + 1] = v.y;
            xs[r][lane * 4 + 2] = v.z;
            xs[r][lane * 4 + 3] = v.w;
        }
    }
    __syncthreads();
    if (tid < 192) {
        int cg = tid >> 4;
        int tg = tid & 15;
        float acc[3][2] = {{0.f,0.f},{0.f,0.f},{0.f,0.f}};
        const float4* Ps4 = (const float4*)Ps;
        const float* r0 = &xs[tg * 2 + 0][0];
        const float* r1 = &xs[tg * 2 + 1][0];
        for (int dd4 = 0; dd4 < 32; dd4++) {
            float4 a0 = Ps4[(cg * 3 + 0) * 32 + dd4];
            float4 a1 = Ps4[(cg * 3 + 1) * 32 + dd4];
            float4 a2 = Ps4[(cg * 3 + 2) * 32 + dd4];
            float b00 = r0[dd4 * 4 + 0], b01 = r0[dd4 * 4 + 1];
            float b02 = r0[dd4 * 4 + 2], b03 = r0[dd4 * 4 + 3];
            float b10 = r1[dd4 * 4 + 0], b11 = r1[dd4 * 4 + 1];
            float b12 = r1[dd4 * 4 + 2], b13 = r1[dd4 * 4 + 3];
            acc[0][0] = fmaf(a0.x, b00, fmaf(a0.y, b01, fmaf(a0.z, b02, fmaf(a0.w, b03, acc[0][0]))));
            acc[0][1] = fmaf(a0.x, b10, fmaf(a0.y, b11, fmaf(a0.z, b12, fmaf(a0.w, b13, acc[0][1]))));
            acc[1][0] = fmaf(a1.x, b00, fmaf(a1.y, b01, fmaf(a1.z, b02, fmaf(a1.w, b03, acc[1][0]))));
            acc[1][1] = fmaf(a1.x, b10, fmaf(a1.y, b11, fmaf(a1.z, b12, fmaf(a1.w, b13, acc[1][1]))));
            acc[2][0] = fmaf(a2.x, b00, fmaf(a2.y, b01, fmaf(a2.z, b02, fmaf(a2.w, b03, acc[2][0]))));
            acc[2][1] = fmaf(a2.x, b10, fmaf(a2.y, b11, fmaf(a2.z, b12, fmaf(a2.w, b13, acc[2][1]))));
        }
        #pragma unroll
        for (int i = 0; i < 3; i++)
            #pragma unroll
            for (int j = 0; j < 2; j++) {
                int c = cg * 3 + i;
                int tl = tg * 2 + j;
                int t = t0 + tl;
                float v = acc[i][j];
                if (c < 4)       dts[c][tl] = v;
                else if (c < 20) g_BC[(size_t)(k * LL + t) * NS + (c - 4)].x = v;
                else             g_BC[(size_t)(k * LL + t) * NS + (c - 20)].y = v;
            }
    }
    __syncthreads();
    {
        int t = tid & 31;
        int w = tid >> 5;
        #pragma unroll
        for (int it = 0; it < 16; it++) {
            int d = w + 8 * it;
            float acc = dt_b[k * 128 + d];
            #pragma unroll
            for (int r = 0; r < 4; r++)
                acc = fmaf(dt_w[(k * 128 + d) * 4 + r], dts[r][t], acc);
            float delta = (acc > 20.f) ? acc : log1pf(__expf(acc));
            float u = xs[t][d];
            g_dd[(size_t)(k * 128 + d) * LL + t0 + t] = make_float2(delta, delta * u);
        }
    }
}

// ---------------- scan pass 1: [n][t] smem B, float4 everywhere ----------------
__global__ void __launch_bounds__(512) k_scan1(const float* __restrict__ A_logs) {
    __shared__ __align__(16) float bbT[16 * 76];    // stride 76: float4-aligned, low conflict
    int tid = threadIdx.x;
    int wl = tid >> 5;
    int ln = tid & 31;
    int k = blockIdx.z, chunk = blockIdx.y, xh = blockIdx.x;
    int dp = xh * 16 + wl;
    int half = ln >> 4, n = ln & 15;
    int d = dp + (half << 6);
    int ch = k * 128 + d;
    int tbeg = chunk * LC;

    const float2* srcBC = g_BC + (size_t)(k * LL + tbeg) * NS;
    for (int i = tid; i < LC * 16; i += 512) {
        int t = i >> 4, nn = i & 15;
        bbT[nn * 76 + t] = srcBC[i].x;
    }
    __syncthreads();

    const float4* pDD4 = (const float4*)(g_dd + (size_t)ch * LL + tbeg);
    const float4* pB4 = (const float4*)(bbT + n * 76);
    float cA = -expf(A_logs[ch * 16 + n]) * 1.44269504f;
    float x = 0.f, sdelta = 0.f;
    #pragma unroll 4
    for (int s4 = 0; s4 < LC / 4; s4++) {
        float4 b4 = pB4[s4];
        float4 q0 = pDD4[2 * s4];
        float4 q1 = pDD4[2 * s4 + 1];
        float dA;
        asm("ex2.approx.ftz.f32 %0, %1;" : "=f"(dA) : "f"(q0.x * cA));
        x = fmaf(dA, x, q0.y * b4.x);
        asm("ex2.approx.ftz.f32 %0, %1;" : "=f"(dA) : "f"(q0.z * cA));
        x = fmaf(dA, x, q0.w * b4.y);
        asm("ex2.approx.ftz.f32 %0, %1;" : "=f"(dA) : "f"(q1.x * cA));
        x = fmaf(dA, x, q1.y * b4.z);
        asm("ex2.approx.ftz.f32 %0, %1;" : "=f"(dA) : "f"(q1.z * cA));
        x = fmaf(dA, x, q1.w * b4.w);
        sdelta += (q0.x + q0.z) + (q1.x + q1.z);
    }
    float ap;
    asm("ex2.approx.ftz.f32 %0, %1;" : "=f"(ap) : "f"(sdelta * cA));
    g_chk[((size_t)ch * CHK + chunk) * NS + n] = make_float2(x, ap);
}

// ---------------- scan pass 2: chunk summaries -> initial states ----------------
__global__ void k_scan2() {
    int idx = blockIdx.x * 256 + threadIdx.x;
    if (idx >= NCH * NS) return;
    int ch = idx >> 4;
    int n  = idx & 15;
    float carry = 0.f;
    #pragma unroll 8
    for (int c = 0; c < CHK; c++) {
        size_t off = ((size_t)ch * CHK + c) * NS + n;
        float2 f = g_chk[off];
        g_init[off] = carry;
        carry = fmaf(f.y, carry, f.x);
    }
}

// ---------------- scan pass 3: [n][t] smem B/C float4, smem y-assembly ----------------
__global__ void __launch_bounds__(1024) k_scan3(const float* __restrict__ A_logs) {
    __shared__ __align__(16) float BsmT[16 * 76];
    __shared__ __align__(16) float CsmT[16 * 76];
    __shared__ float xc[32][8][33];
    __shared__ float ytile[8 * 65];
    int tid = threadIdx.x;
    int wl = tid >> 5;
    int ln = tid & 31;
    int k = blockIdx.z, chunk = blockIdx.y, xh = blockIdx.x;
    int dp = xh * 32 + wl;
    int half = ln >> 4, n = ln & 15;
    int d = dp + (half << 6);
    int ch = k * 128 + d;
    int tbeg = chunk * LC;

    {
        const float2* srcBC = g_BC + (size_t)(k * LL + tbeg) * NS;
        if (tid < LC * 16) {
            int t = tid >> 4, nn = tid & 15;
            float2 v = srcBC[tid];
            BsmT[nn * 76 + t] = v.x;
            CsmT[nn * 76 + t] = v.y;
        }
    }
    __syncthreads();

    const float4* pDD4 = (const float4*)(g_dd + (size_t)ch * LL + tbeg);
    const float4* pB4 = (const float4*)(BsmT + n * 76);
    const float4* pC4 = (const float4*)(CsmT + n * 76);
    float cA = -expf(A_logs[ch * 16 + n]) * 1.44269504f;
    float x = g_init[((size_t)ch * CHK + chunk) * NS + n];

    int rc = ln >> 4;
    int rj = (ln >> 1) & 7;
    int rh = ln & 1;
    int sr = tid >> 6;
    int sc = tid & 63;
    int sd = xh * 32 + (sc & 31) + ((sc >> 5) << 6);
    float* ydst0 = g_y + (size_t)(k * LL + tbeg) * 128 + sd;

    for (int t0 = 0; t0 < LC; t0 += 8) {
        #pragma unroll
        for (int v = 0; v < 2; v++) {
            float4 b4 = pB4[(t0 >> 2) + v];
            float4 c4 = pC4[(t0 >> 2) + v];
            float4 q0 = pDD4[(t0 >> 1) + 2 * v];
            float4 q1 = pDD4[(t0 >> 1) + 2 * v + 1];
            int s = (4 * v) & 7;
            float dA;
            asm("ex2.approx.ftz.f32 %0, %1;" : "=f"(dA) : "f"(q0.x * cA));
            x = fmaf(dA, x, q0.y * b4.x);
            xc[wl][s + 0][ln] = x * c4.x;
            asm("ex2.approx.ftz.f32 %0, %1;" : "=f"(dA) : "f"(q0.z * cA));
            x = fmaf(dA, x, q0.w * b4.y);
            xc[wl][s + 1][ln] = x * c4.y;
            asm("ex2.approx.ftz.f32 %0, %1;" : "=f"(dA) : "f"(q1.x * cA));
            x = fmaf(dA, x, q1.y * b4.z);
            xc[wl][s + 2][ln] = x * c4.z;
            asm("ex2.approx.ftz.f32 %0, %1;" : "=f"(dA) : "f"(q1.z * cA));
            x = fmaf(dA, x, q1.w * b4.w);
            xc[wl][s + 3][ln] = x * c4.w;
        }
        __syncwarp();
        float sum = 0.f;
        #pragma unroll
        for (int m = 0; m < 8; m++)
            sum += xc[wl][rj][rc * 16 + rh * 8 + m];
        sum += __shfl_xor_sync(0xffffffffu, sum, 1);
        if (rh == 0) ytile[rj * 65 + rc * 32 + wl] = sum;
        __syncthreads();
        if (tid < 512) ydst0[(size_t)(t0 + sr) * 128] = ytile[sr * 65 + sc];
        __syncthreads();
    }
}

// ---------------- combine: 4 concurrent positions per block ----------------
__global__ void __launch_bounds__(512) k_comb(const float* __restrict__ Ds,
                                              const float* __restrict__ ln_g,
                                              const float* __restrict__ ln_b,
                                              const float* __restrict__ W_out,
                                              float* __restrict__ out) {
    __shared__ __align__(16) float Wsm[64 * 132];
    __shared__ __align__(16) float gsm[4][132];
    __shared__ float red[4][8];
    __shared__ float mus[4][2];
    __shared__ int ism[6 * 16];
    int tid = threadIdx.x;
    int g = tid >> 7;
    int gt = tid & 127;
    for (int i = tid; i < 64 * 128; i += 512)
        Wsm[(i >> 7) * 132 + (i & 127)] = W_out[i];
    if (tid < 96) {
        int kk = tid >> 4, jj = tid & 15;
        ism[kk * 16 + jj] = iout_idx(kk, blockIdx.x * 16 + jj);
    }
    int d = gt;
    float dsum = 0.f;
    #pragma unroll
    for (int k = 0; k < 5; k++) dsum += Ds[k * 128 + d];
    float d5 = Ds[5 * 128 + d];
    float gg = ln_g[d], bb = ln_b[d];
    int lane = tid & 31;
    int wg = gt >> 5;
    int oo = (wg << 4) + (lane & 15);
    int hh2 = lane >> 4;
    __syncthreads();

    for (int it = 0; it < 4; it++) {
        int jj = it * 4 + g;
        int j = blockIdx.x * 16 + jj;
        float y = 0.f;
        #pragma unroll
        for (int k = 0; k < 6; k++)
            y += g_y[(size_t)(k * LL + ism[k * 16 + jj]) * 128 + d];
        int fl = ((63 - (j >> 6)) << 6) | (j & 63);
        y += dsum * g_xcT[j * 128 + d] + d5 * g_xcT[fl * 128 + d];
        float s1 = y, s2 = y * y;
        #pragma unroll
        for (int o = 16; o; o >>= 1) {
            s1 += __shfl_xor_sync(0xffffffffu, s1, o);
            s2 += __shfl_xor_sync(0xffffffffu, s2, o);
        }
        if (lane == 0) { red[g][wg] = s1; red[g][4 + wg] = s2; }
        __syncthreads();
        if (gt == 0) {
            float S1 = red[g][0] + red[g][1] + red[g][2] + red[g][3];
            float S2 = red[g][4] + red[g][5] + red[g][6] + red[g][7];
            float mu = S1 * (1.f / 128.f);
            float var = S2 * (1.f / 128.f) - mu * mu;
            mus[g][0] = mu;
            mus[g][1] = rsqrtf(var + 1e-5f);
        }
        __syncthreads();
        float yn = (y - mus[g][0]) * mus[g][1] * gg + bb;
        float z = g_z[j * 128 + d];
        gsm[g][d] = yn * (z / (1.f + __expf(-z)));
        __syncthreads();
        {
            float acc = 0.f;
            const float4* wrow = (const float4*)(Wsm + oo * 132 + (hh2 << 6));
            const float4* grow = (const float4*)(gsm[g] + (hh2 << 6));
            #pragma unroll
            for (int q = 0; q < 16; q++) {
                float4 wv = wrow[q];
                float4 gv = grow[q];
                acc = fmaf(wv.x, gv.x, fmaf(wv.y, gv.y, fmaf(wv.z, gv.z, fmaf(wv.w, gv.w, acc))));
            }
            acc += __shfl_xor_sync(0xffffffffu, acc, 16);
            if (hh2 == 0) out[j * 64 + oo] = acc;
        }
        __syncthreads();
    }
}

// ---------------- launch ----------------
extern "C" void kernel_launch(void* const* d_in, const int* in_sizes, int n_in,
                              void* d_out, int out_size) {
    const float* x        = (const float*)d_in[0];
    const float* W_in     = (const float*)d_in[1];
    const float* conv_w   = (const float*)d_in[2];
    const float* conv_b   = (const float*)d_in[3];
    const float* x_proj_w = (const float*)d_in[4];
    const float* dt_w     = (const float*)d_in[5];
    const float* dt_b     = (const float*)d_in[6];
    const float* A_logs   = (const float*)d_in[7];
    const float* Ds       = (const float*)d_in[8];
    const float* ln_g     = (const float*)d_in[9];
    const float* ln_b     = (const float*)d_in[10];
    const float* W_out    = (const float*)d_in[11];
    float* out = (float*)d_out;

    k_inproj<<<128, 256>>>(x, W_in);
    k_conv<<<(LL * 64) / 256, 256>>>(conv_w, conv_b);
    {
        dim3 g(LL / 32, KDIR);
        k_proj<<<g, 256>>>(x_proj_w, dt_w, dt_b);
    }
    {
        dim3 g1(4, CHK, KDIR);
        k_scan1<<<g1, 512>>>(A_logs);
        k_scan2<<<48, 256>>>();
        dim3 g3(2, CHK, KDIR);
        k_scan3<<<g3, 1024>>>(A_logs);
    }
    k_comb<<<256, 512>>>(Ds, ln_g, ln_b, W_out, out);
}

// round 11
// speedup vs baseline: 1.9479x; 1.0483x over previous
#include <cuda_runtime.h>
#include <cuda_bf16.h>
#include <math.h>

#define KDIR 6
#define LL 4096
#define DI 128
#define NS 16
#define DTR 4
#define NCH (KDIR * DI)
#define CHK 64
#define LC  (LL / CHK)         // 64

// ---------------- scratch ----------------
__device__ float  g_xx[LL * DI];
__device__ float  g_z [LL * DI];
__device__ float  g_xcT[LL * DI];
__device__ float2 g_BC[KDIR * LL * NS];   // (B,C), [k][t][n] interleaved
__device__ float2 g_dd[KDIR * DI * LL];   // (delta, delta*u), [k][d][t]
__device__ float  g_y [KDIR * LL * DI];   // [k][t][d]
__device__ float2 g_chk [NCH * CHK * NS];
__device__ float  g_init[NCH * CHK * NS];

// ---------------- closed-form diagonal permutation ----------------
__device__ __forceinline__ int dg_low(int r) {
    int dg = (int)((sqrtf((float)(8 * r + 1)) - 1.f) * 0.5f);
    while (((dg + 1) * (dg + 2)) >> 1 <= r) dg++;
    while ((dg * (dg + 1)) >> 1 > r) dg--;
    return dg;
}
__device__ __forceinline__ int diag_t(int r) {
    int i, dg;
    if (r < 2080) { dg = dg_low(r); i = r - ((dg * (dg + 1)) >> 1); }
    else {
        int q = 4095 - r;
        int dgm = dg_low(q);
        int p = q - ((dgm * (dgm + 1)) >> 1);
        i = 63 - p;
        dg = 126 - dgm;
    }
    int j = dg - i;
    return (i << 6) | j;
}
__device__ __forceinline__ int rev_idx(int t) {
    int i = t >> 6, c = t & 63, dg = i + c;
    int cum = (dg < 64) ? ((dg * (dg + 1)) >> 1)
                        : 4096 - (((127 - dg) * (128 - dg)) >> 1);
    int lo = dg - 63; if (lo < 0) lo = 0;
    return cum + i - lo;
}
__device__ __forceinline__ int sin_idx(int k, int t) {
    switch (k) {
        case 0: return t;
        case 1: return ((t & 63) << 6) | (t >> 6);
        case 2: return 4095 - t;
        case 3: { int t2 = 4095 - t; return ((t2 & 63) << 6) | (t2 >> 6); }
        case 4: return diag_t(t);
        default: return diag_t(t) ^ 63;
    }
}
__device__ __forceinline__ int iout_idx(int k, int j) {
    switch (k) {
        case 0: return j;
        case 1: return ((j & 63) << 6) | (j >> 6);
        case 2: return 4095 - j;
        case 3: return 4095 - (((j & 63) << 6) | (j >> 6));
        case 4: return rev_idx(j);
        default: return rev_idx(4095 - j);
    }
}

// ---------------- in_proj GEMM ----------------
__global__ void __launch_bounds__(256) k_inproj(const float* __restrict__ x,
                                                const float* __restrict__ W_in) {
    __shared__ float Wsm[128 * 65];
    __shared__ float xsm[32 * 65];
    int tid = threadIdx.x;
    int l0 = blockIdx.x * 32;
    for (int i = tid; i < 32 * 64; i += 256)
        xsm[(i >> 6) * 65 + (i & 63)] = x[(l0 + (i >> 6)) * 64 + (i & 63)];
    int og = tid & 31;
    int lg = tid >> 5;
    for (int ot = 0; ot < 2; ot++) {
        __syncthreads();
        for (int i = tid; i < 128 * 64; i += 256)
            Wsm[(i >> 6) * 65 + (i & 63)] = W_in[(ot * 128 + (i >> 6)) * 64 + (i & 63)];
        __syncthreads();
        float acc[4][4];
        #pragma unroll
        for (int i = 0; i < 4; i++)
            #pragma unroll
            for (int ii = 0; ii < 4; ii++) acc[i][ii] = 0.f;
        for (int c = 0; c < 64; c++) {
            float wv[4], xv[4];
            #pragma unroll
            for (int i = 0; i < 4; i++)  wv[i]  = Wsm[(og + 32 * i) * 65 + c];
            #pragma unroll
            for (int ii = 0; ii < 4; ii++) xv[ii] = xsm[(lg + 8 * ii) * 65 + c];
            #pragma unroll
            for (int i = 0; i < 4; i++)
                #pragma unroll
                for (int ii = 0; ii < 4; ii++)
                    acc[i][ii] = fmaf(wv[i], xv[ii], acc[i][ii]);
        }
        float* dst = (ot == 0) ? g_xx : g_z;
        #pragma unroll
        for (int i = 0; i < 4; i++)
            #pragma unroll
            for (int ii = 0; ii < 4; ii++)
                dst[(l0 + lg + 8 * ii) * 128 + og + 32 * i] = acc[i][ii];
    }
}

// ---------------- depthwise 3x3 conv + bias + SiLU ----------------
__global__ void __launch_bounds__(256) k_conv(const float* __restrict__ conv_w,
                                              const float* __restrict__ conv_b) {
    __shared__ float2 cw[9 * 64];
    __shared__ float2 cb[64];
    int tid = threadIdx.x;
    for (int i = tid; i < 9 * 64; i += 256) {
        int tap = i >> 6, d2 = i & 63;
        cw[i] = make_float2(conv_w[(2 * d2) * 9 + tap], conv_w[(2 * d2 + 1) * 9 + tap]);
    }
    if (tid < 64) cb[tid] = ((const float2*)conv_b)[tid];
    __syncthreads();
    int idx = blockIdx.x * 256 + tid;
    int d2 = idx & 63;
    int l = idx >> 6;
    int h = l >> 6, w = l & 63;
    float2 acc = cb[d2];
    const float2* xx2 = (const float2*)g_xx;
    #pragma unroll
    for (int kh = -1; kh <= 1; kh++) {
        int hh = h + kh;
        if ((unsigned)hh >= 64u) continue;
        #pragma unroll
        for (int kw = -1; kw <= 1; kw++) {
            int wc = w + kw;
            if ((unsigned)wc >= 64u) continue;
            float2 v = xx2[((hh << 6) | wc) * 64 + d2];
            float2 cc = cw[((kh + 1) * 3 + (kw + 1)) * 64 + d2];
            acc.x = fmaf(cc.x, v.x, acc.x);
            acc.y = fmaf(cc.y, v.y, acc.y);
        }
    }
    acc.x = acc.x / (1.f + __expf(-acc.x));
    acc.y = acc.y / (1.f + __expf(-acc.y));
    ((float2*)g_xcT)[l * 64 + d2] = acc;
}

// ---------------- projection + fused delta ----------------
__global__ void __launch_bounds__(256) k_proj(const float* __restrict__ x_proj_w,
                                              const float* __restrict__ dt_w,
                                              const float* __restrict__ dt_b) {
    __shared__ float xs[32][129];
    __shared__ __align__(16) float Ps[36 * 128];
    __shared__ float dts[4][32];
    __shared__ int sidx[32];
    int k  = blockIdx.y;
    int t0 = blockIdx.x * 32;
    int tid = threadIdx.x;
    if (tid < 32) sidx[tid] = sin_idx(k, t0 + tid);
    __syncthreads();
    for (int i = tid; i < 36 * 128; i += 256)
        Ps[i] = x_proj_w[k * 36 * 128 + i];
    {
        int lane = tid & 31;
        for (int r = tid >> 5; r < 32; r += 8) {
            int s = sidx[r];
            const float4* src = (const float4*)(g_xcT + s * 128);
            float4 v = src[lane];
            xs[r][lane * 4 + 0] = v.x;
            xs[r][lane * 4 + 1] = v.y;
            xs[r][lane * 4 + 2] = v.z;
            xs[r][lane * 4 + 3] = v.w;
        }
    }
    __syncthreads();
    if (tid < 192) {
        int cg = tid >> 4;
        int tg = tid & 15;
        float acc[3][2] = {{0.f,0.f},{0.f,0.f},{0.f,0.f}};
        const float4* Ps4 = (const float4*)Ps;
        const float* r0 = &xs[tg * 2 + 0][0];
        const float* r1 = &xs[tg * 2 + 1][0];
        for (int dd4 = 0; dd4 < 32; dd4++) {
            float4 a0 = Ps4[(cg * 3 + 0) * 32 + dd4];
            float4 a1 = Ps4[(cg * 3 + 1) * 32 + dd4];
            float4 a2 = Ps4[(cg * 3 + 2) * 32 + dd4];
            float b00 = r0[dd4 * 4 + 0], b01 = r0[dd4 * 4 + 1];
            float b02 = r0[dd4 * 4 + 2], b03 = r0[dd4 * 4 + 3];
            float b10 = r1[dd4 * 4 + 0], b11 = r1[dd4 * 4 + 1];
            float b12 = r1[dd4 * 4 + 2], b13 = r1[dd4 * 4 + 3];
            acc[0][0] = fmaf(a0.x, b00, fmaf(a0.y, b01, fmaf(a0.z, b02, fmaf(a0.w, b03, acc[0][0]))));
            acc[0][1] = fmaf(a0.x, b10, fmaf(a0.y, b11, fmaf(a0.z, b12, fmaf(a0.w, b13, acc[0][1]))));
            acc[1][0] = fmaf(a1.x, b00, fmaf(a1.y, b01, fmaf(a1.z, b02, fmaf(a1.w, b03, acc[1][0]))));
            acc[1][1] = fmaf(a1.x, b10, fmaf(a1.y, b11, fmaf(a1.z, b12, fmaf(a1.w, b13, acc[1][1]))));
            acc[2][0] = fmaf(a2.x, b00, fmaf(a2.y, b01, fmaf(a2.z, b02, fmaf(a2.w, b03, acc[2][0]))));
            acc[2][1] = fmaf(a2.x, b10, fmaf(a2.y, b11, fmaf(a2.z, b12, fmaf(a2.w, b13, acc[2][1]))));
        }
        #pragma unroll
        for (int i = 0; i < 3; i++)
            #pragma unroll
            for (int j = 0; j < 2; j++) {
                int c = cg * 3 + i;
                int tl = tg * 2 + j;
                int t = t0 + tl;
                float v = acc[i][j];
                if (c < 4)       dts[c][tl] = v;
                else if (c < 20) g_BC[(size_t)(k * LL + t) * NS + (c - 4)].x = v;
                else             g_BC[(size_t)(k * LL + t) * NS + (c - 20)].y = v;
            }
    }
    __syncthreads();
    {
        int t = tid & 31;
        int w = tid >> 5;
        #pragma unroll
        for (int it = 0; it < 16; it++) {
            int d = w + 8 * it;
            float acc = dt_b[k * 128 + d];
            #pragma unroll
            for (int r = 0; r < 4; r++)
                acc = fmaf(dt_w[(k * 128 + d) * 4 + r], dts[r][t], acc);
            float delta = (acc > 20.f) ? acc : log1pf(__expf(acc));
            float u = xs[t][d];
            g_dd[(size_t)(k * 128 + d) * LL + t0 + t] = make_float2(delta, delta * u);
        }
    }
}

// ---------------- scan pass 1: smem B [t][n], prefetched float4 dd ----------------
__global__ void __launch_bounds__(512) k_scan1(const float* __restrict__ A_logs) {
    __shared__ float bb[LC * 16];          // 4 KB, [t][n]
    int tid = threadIdx.x;
    int wl = tid >> 5;
    int ln = tid & 31;
    int k = blockIdx.z, chunk = blockIdx.y, xh = blockIdx.x;
    int dp = xh * 16 + wl;
    int half = ln >> 4, n = ln & 15;
    int d = dp + (half << 6);
    int ch = k * 128 + d;
    int tbeg = chunk * LC;

    {
        const float4* src4 = (const float4*)(g_BC + (size_t)(k * LL + tbeg) * NS);
        if (tid < 512) {
            float4 v = src4[tid];
            bb[2 * tid]     = v.x;
            bb[2 * tid + 1] = v.z;
        }
    }
    __syncthreads();

    const float4* pDD4 = (const float4*)(g_dd + (size_t)ch * LL + tbeg);
    float cA = -expf(A_logs[ch * 16 + n]) * 1.44269504f;
    float x = 0.f, sdelta = 0.f;
    float4 q0 = pDD4[0], q1 = pDD4[1];
    #pragma unroll 5
    for (int s4 = 0; s4 < LC / 4 - 1; s4++) {
        float4 n0 = pDD4[2 * s4 + 2];
        float4 n1 = pDD4[2 * s4 + 3];
        int t4 = 4 * s4;
        float dA;
        asm("ex2.approx.ftz.f32 %0, %1;" : "=f"(dA) : "f"(q0.x * cA));
        x = fmaf(dA, x, q0.y * bb[(t4 + 0) * 16 + n]);
        asm("ex2.approx.ftz.f32 %0, %1;" : "=f"(dA) : "f"(q0.z * cA));
        x = fmaf(dA, x, q0.w * bb[(t4 + 1) * 16 + n]);
        asm("ex2.approx.ftz.f32 %0, %1;" : "=f"(dA) : "f"(q1.x * cA));
        x = fmaf(dA, x, q1.y * bb[(t4 + 2) * 16 + n]);
        asm("ex2.approx.ftz.f32 %0, %1;" : "=f"(dA) : "f"(q1.z * cA));
        x = fmaf(dA, x, q1.w * bb[(t4 + 3) * 16 + n]);
        sdelta += (q0.x + q0.z) + (q1.x + q1.z);
        q0 = n0; q1 = n1;
    }
    {   // peeled last 4 steps
        int t4 = LC - 4;
        float dA;
        asm("ex2.approx.ftz.f32 %0, %1;" : "=f"(dA) : "f"(q0.x * cA));
        x = fmaf(dA, x, q0.y * bb[(t4 + 0) * 16 + n]);
        asm("ex2.approx.ftz.f32 %0, %1;" : "=f"(dA) : "f"(q0.z * cA));
        x = fmaf(dA, x, q0.w * bb[(t4 + 1) * 16 + n]);
        asm("ex2.approx.ftz.f32 %0, %1;" : "=f"(dA) : "f"(q1.x * cA));
        x = fmaf(dA, x, q1.y * bb[(t4 + 2) * 16 + n]);
        asm("ex2.approx.ftz.f32 %0, %1;" : "=f"(dA) : "f"(q1.z * cA));
        x = fmaf(dA, x, q1.w * bb[(t4 + 3) * 16 + n]);
        sdelta += (q0.x + q0.z) + (q1.x + q1.z);
    }
    float ap;
    asm("ex2.approx.ftz.f32 %0, %1;" : "=f"(ap) : "f"(sdelta * cA));
    g_chk[((size_t)ch * CHK + chunk) * NS + n] = make_float2(x, ap);
}

// ---------------- scan pass 2: chunk summaries -> initial states ----------------
__global__ void k_scan2() {
    int idx = blockIdx.x * 256 + threadIdx.x;
    if (idx >= NCH * NS) return;
    int ch = idx >> 4;
    int n  = idx & 15;
    float carry = 0.f;
    #pragma unroll 8
    for (int c = 0; c < CHK; c++) {
        size_t off = ((size_t)ch * CHK + c) * NS + n;
        float2 f = g_chk[off];
        g_init[off] = carry;
        carry = fmaf(f.y, carry, f.x);
    }
}

// ---------------- scan pass 3: 512-thread blocks, batched loads, smem y-assembly ----------------
__global__ void __launch_bounds__(512) k_scan3(const float* __restrict__ A_logs) {
    __shared__ __align__(16) float BsmT[16 * 76];
    __shared__ __align__(16) float CsmT[16 * 76];
    __shared__ float xc[16][8][33];        // 16.9 KB
    __shared__ float ytile[8 * 33];
    int tid = threadIdx.x;
    int wl = tid >> 5;                     // 0..15
    int ln = tid & 31;
    int k = blockIdx.z, chunk = blockIdx.y, xh = blockIdx.x;
    int dp = xh * 16 + wl;
    int half = ln >> 4, n = ln & 15;
    int d = dp + (half << 6);
    int ch = k * 128 + d;
    int tbeg = chunk * LC;

    {
        const float2* srcBC = g_BC + (size_t)(k * LL + tbeg) * NS;
        for (int i = tid; i < LC * 16; i += 512) {
            int t = i >> 4, nn = i & 15;
            float2 v = srcBC[i];
            BsmT[nn * 76 + t] = v.x;
            CsmT[nn * 76 + t] = v.y;
        }
    }
    __syncthreads();

    const float4* pDD4 = (const float4*)(g_dd + (size_t)ch * LL + tbeg);
    const float4* pB4 = (const float4*)(BsmT + n * 76);
    const float4* pC4 = (const float4*)(CsmT + n * 76);
    float cA = -expf(A_logs[ch * 16 + n]) * 1.44269504f;
    float x = g_init[((size_t)ch * CHK + chunk) * NS + n];

    int rc = ln >> 4;
    int rj = (ln >> 1) & 7;
    int rh = ln & 1;
    int sr = tid >> 5;         // 0..15 (only 0..7 used for stores)
    int sc = tid & 31;
    int sd = xh * 16 + (sc & 15) + ((sc >> 4) << 6);
    float* ydst0 = g_y + (size_t)(k * LL + tbeg) * 128 + sd;

    for (int t0 = 0; t0 < LC; t0 += 8) {
        // batch the window's loads up front (MLP 4 on dd)
        float4 q0 = pDD4[(t0 >> 1) + 0];
        float4 q1 = pDD4[(t0 >> 1) + 1];
        float4 q2 = pDD4[(t0 >> 1) + 2];
        float4 q3 = pDD4[(t0 >> 1) + 3];
        float4 b40 = pB4[(t0 >> 2) + 0];
        float4 b41 = pB4[(t0 >> 2) + 1];
        float4 c40 = pC4[(t0 >> 2) + 0];
        float4 c41 = pC4[(t0 >> 2) + 1];
        float dA;
        asm("ex2.approx.ftz.f32 %0, %1;" : "=f"(dA) : "f"(q0.x * cA));
        x = fmaf(dA, x, q0.y * b40.x);
        xc[wl][0][ln] = x * c40.x;
        asm("ex2.approx.ftz.f32 %0, %1;" : "=f"(dA) : "f"(q0.z * cA));
        x = fmaf(dA, x, q0.w * b40.y);
        xc[wl][1][ln] = x * c40.y;
        asm("ex2.approx.ftz.f32 %0, %1;" : "=f"(dA) : "f"(q1.x * cA));
        x = fmaf(dA, x, q1.y * b40.z);
        xc[wl][2][ln] = x * c40.z;
        asm("ex2.approx.ftz.f32 %0, %1;" : "=f"(dA) : "f"(q1.z * cA));
        x = fmaf(dA, x, q1.w * b40.w);
        xc[wl][3][ln] = x * c40.w;
        asm("ex2.approx.ftz.f32 %0, %1;" : "=f"(dA) : "f"(q2.x * cA));
        x = fmaf(dA, x, q2.y * b41.x);
        xc[wl][4][ln] = x * c41.x;
        asm("ex2.approx.ftz.f32 %0, %1;" : "=f"(dA) : "f"(q2.z * cA));
        x = fmaf(dA, x, q2.w * b41.y);
        xc[wl][5][ln] = x * c41.y;
        asm("ex2.approx.ftz.f32 %0, %1;" : "=f"(dA) : "f"(q3.x * cA));
        x = fmaf(dA, x, q3.y * b41.z);
        xc[wl][6][ln] = x * c41.z;
        asm("ex2.approx.ftz.f32 %0, %1;" : "=f"(dA) : "f"(q3.z * cA));
        x = fmaf(dA, x, q3.w * b41.w);
        xc[wl][7][ln] = x * c41.w;
        __syncwarp();
        float sum = 0.f;
        #pragma unroll
        for (int m = 0; m < 8; m++)
            sum += xc[wl][rj][rc * 16 + rh * 8 + m];
        sum += __shfl_xor_sync(0xffffffffu, sum, 1);
        if (rh == 0) ytile[rj * 33 + rc * 16 + wl] = sum;
        __syncthreads();
        if (tid < 256) ydst0[(size_t)(t0 + sr) * 128] = ytile[sr * 33 + sc];
        __syncthreads();
    }
}

// ---------------- combine: 4 concurrent positions per block ----------------
__global__ void __launch_bounds__(512) k_comb(const float* __restrict__ Ds,
                                              const float* __restrict__ ln_g,
                                              const float* __restrict__ ln_b,
                                              const float* __restrict__ W_out,
                                              float* __restrict__ out) {
    __shared__ __align__(16) float Wsm[64 * 132];
    __shared__ __align__(16) float gsm[4][132];
    __shared__ float red[4][8];
    __shared__ float mus[4][2];
    __shared__ int ism[6 * 16];
    int tid = threadIdx.x;
    int g = tid >> 7;
    int gt = tid & 127;
    for (int i = tid; i < 64 * 128; i += 512)
        Wsm[(i >> 7) * 132 + (i & 127)] = W_out[i];
    if (tid < 96) {
        int kk = tid >> 4, jj = tid & 15;
        ism[kk * 16 + jj] = iout_idx(kk, blockIdx.x * 16 + jj);
    }
    int d = gt;
    float dsum = 0.f;
    #pragma unroll
    for (int k = 0; k < 5; k++) dsum += Ds[k * 128 + d];
    float d5 = Ds[5 * 128 + d];
    float gg = ln_g[d], bb = ln_b[d];
    int lane = tid & 31;
    int wg = gt >> 5;
    int oo = (wg << 4) + (lane & 15);
    int hh2 = lane >> 4;
    __syncthreads();

    for (int it = 0; it < 4; it++) {
        int jj = it * 4 + g;
        int j = blockIdx.x * 16 + jj;
        float y = 0.f;
        #pragma unroll
        for (int k = 0; k < 6; k++)
            y += g_y[(size_t)(k * LL + ism[k * 16 + jj]) * 128 + d];
        int fl = ((63 - (j >> 6)) << 6) | (j & 63);
        y += dsum * g_xcT[j * 128 + d] + d5 * g_xcT[fl * 128 + d];
        float s1 = y, s2 = y * y;
        #pragma unroll
        for (int o = 16; o; o >>= 1) {
            s1 += __shfl_xor_sync(0xffffffffu, s1, o);
            s2 += __shfl_xor_sync(0xffffffffu, s2, o);
        }
        if (lane == 0) { red[g][wg] = s1; red[g][4 + wg] = s2; }
        __syncthreads();
        if (gt == 0) {
            float S1 = red[g][0] + red[g][1] + red[g][2] + red[g][3];
            float S2 = red[g][4] + red[g][5] + red[g][6] + red[g][7];
            float mu = S1 * (1.f / 128.f);
            float var = S2 * (1.f / 128.f) - mu * mu;
            mus[g][0] = mu;
            mus[g][1] = rsqrtf(var + 1e-5f);
        }
        __syncthreads();
        float yn = (y - mus[g][0]) * mus[g][1] * gg + bb;
        float z = g_z[j * 128 + d];
        gsm[g][d] = yn * (z / (1.f + __expf(-z)));
        __syncthreads();
        {
            float acc = 0.f;
            const float4* wrow = (const float4*)(Wsm + oo * 132 + (hh2 << 6));
            const float4* grow = (const float4*)(gsm[g] + (hh2 << 6));
            #pragma unroll
            for (int q = 0; q < 16; q++) {
                float4 wv = wrow[q];
                float4 gv = grow[q];
                acc = fmaf(wv.x, gv.x, fmaf(wv.y, gv.y, fmaf(wv.z, gv.z, fmaf(wv.w, gv.w, acc))));
            }
            acc += __shfl_xor_sync(0xffffffffu, acc, 16);
            if (hh2 == 0) out[j * 64 + oo] = acc;
        }
        __syncthreads();
    }
}

// ---------------- launch ----------------
extern "C" void kernel_launch(void* const* d_in, const int* in_sizes, int n_in,
                              void* d_out, int out_size) {
    const float* x        = (const float*)d_in[0];
    const float* W_in     = (const float*)d_in[1];
    const float* conv_w   = (const float*)d_in[2];
    const float* conv_b   = (const float*)d_in[3];
    const float* x_proj_w = (const float*)d_in[4];
    const float* dt_w     = (const float*)d_in[5];
    const float* dt_b     = (const float*)d_in[6];
    const float* A_logs   = (const float*)d_in[7];
    const float* Ds       = (const float*)d_in[8];
    const float* ln_g     = (const float*)d_in[9];
    const float* ln_b     = (const float*)d_in[10];
    const float* W_out    = (const float*)d_in[11];
    float* out = (float*)d_out;

    k_inproj<<<128, 256>>>(x, W_in);
    k_conv<<<(LL * 64) / 256, 256>>>(conv_w, conv_b);
    {
        dim3 g(LL / 32, KDIR);
        k_proj<<<g, 256>>>(x_proj_w, dt_w, dt_b);
    }
    {
        dim3 gs(4, CHK, KDIR);
        k_scan1<<<gs, 512>>>(A_logs);
        k_scan2<<<48, 256>>>();
        k_scan3<<<gs, 512>>>(A_logs);
    }
    k_comb<<<256, 512>>>(Ds, ln_g, ln_b, W_out, out);
}

// round 12
// speedup vs baseline: 1.9902x; 1.0217x over previous
#include <cuda_runtime.h>
#include <cuda_bf16.h>
#include <math.h>

#define KDIR 6
#define LL 4096
#define DI 128
#define NS 16
#define DTR 4
#define NCH (KDIR * DI)
#define CHK 64
#define LC  (LL / CHK)         // 64

// ---------------- scratch ----------------
__device__ float  g_xx[LL * DI];
__device__ float  g_z [LL * DI];
__device__ float  g_xcT[LL * DI];
__device__ float2 g_BC[KDIR * LL * NS];   // (B,C), [k][t][n] interleaved
__device__ float2 g_dd[KDIR * DI * LL];   // (delta, delta*u), [k][d][t]
__device__ float  g_y [KDIR * LL * DI];   // [k][t][d]
__device__ float2 g_chk [NCH * CHK * NS];
__device__ float  g_init[NCH * CHK * NS];

// ---------------- closed-form diagonal permutation ----------------
__device__ __forceinline__ int dg_low(int r) {
    int dg = (int)((sqrtf((float)(8 * r + 1)) - 1.f) * 0.5f);
    while (((dg + 1) * (dg + 2)) >> 1 <= r) dg++;
    while ((dg * (dg + 1)) >> 1 > r) dg--;
    return dg;
}
__device__ __forceinline__ int diag_t(int r) {
    int i, dg;
    if (r < 2080) { dg = dg_low(r); i = r - ((dg * (dg + 1)) >> 1); }
    else {
        int q = 4095 - r;
        int dgm = dg_low(q);
        int p = q - ((dgm * (dgm + 1)) >> 1);
        i = 63 - p;
        dg = 126 - dgm;
    }
    int j = dg - i;
    return (i << 6) | j;
}
__device__ __forceinline__ int rev_idx(int t) {
    int i = t >> 6, c = t & 63, dg = i + c;
    int cum = (dg < 64) ? ((dg * (dg + 1)) >> 1)
                        : 4096 - (((127 - dg) * (128 - dg)) >> 1);
    int lo = dg - 63; if (lo < 0) lo = 0;
    return cum + i - lo;
}
__device__ __forceinline__ int sin_idx(int k, int t) {
    switch (k) {
        case 0: return t;
        case 1: return ((t & 63) << 6) | (t >> 6);
        case 2: return 4095 - t;
        case 3: { int t2 = 4095 - t; return ((t2 & 63) << 6) | (t2 >> 6); }
        case 4: return diag_t(t);
        default: return diag_t(t) ^ 63;
    }
}
__device__ __forceinline__ int iout_idx(int k, int j) {
    switch (k) {
        case 0: return j;
        case 1: return ((j & 63) << 6) | (j >> 6);
        case 2: return 4095 - j;
        case 3: return 4095 - (((j & 63) << 6) | (j >> 6));
        case 4: return rev_idx(j);
        default: return rev_idx(4095 - j);
    }
}

// ---------------- in_proj GEMM ----------------
__global__ void __launch_bounds__(256) k_inproj(const float* __restrict__ x,
                                                const float* __restrict__ W_in) {
    __shared__ float Wsm[128 * 65];
    __shared__ float xsm[32 * 65];
    int tid = threadIdx.x;
    int l0 = blockIdx.x * 32;
    for (int i = tid; i < 32 * 64; i += 256)
        xsm[(i >> 6) * 65 + (i & 63)] = x[(l0 + (i >> 6)) * 64 + (i & 63)];
    int og = tid & 31;
    int lg = tid >> 5;
    for (int ot = 0; ot < 2; ot++) {
        __syncthreads();
        for (int i = tid; i < 128 * 64; i += 256)
            Wsm[(i >> 6) * 65 + (i & 63)] = W_in[(ot * 128 + (i >> 6)) * 64 + (i & 63)];
        __syncthreads();
        float acc[4][4];
        #pragma unroll
        for (int i = 0; i < 4; i++)
            #pragma unroll
            for (int ii = 0; ii < 4; ii++) acc[i][ii] = 0.f;
        for (int c = 0; c < 64; c++) {
            float wv[4], xv[4];
            #pragma unroll
            for (int i = 0; i < 4; i++)  wv[i]  = Wsm[(og + 32 * i) * 65 + c];
            #pragma unroll
            for (int ii = 0; ii < 4; ii++) xv[ii] = xsm[(lg + 8 * ii) * 65 + c];
            #pragma unroll
            for (int i = 0; i < 4; i++)
                #pragma unroll
                for (int ii = 0; ii < 4; ii++)
                    acc[i][ii] = fmaf(wv[i], xv[ii], acc[i][ii]);
        }
        float* dst = (ot == 0) ? g_xx : g_z;
        #pragma unroll
        for (int i = 0; i < 4; i++)
            #pragma unroll
            for (int ii = 0; ii < 4; ii++)
                dst[(l0 + lg + 8 * ii) * 128 + og + 32 * i] = acc[i][ii];
    }
}

// ---------------- depthwise 3x3 conv + bias + SiLU ----------------
__global__ void __launch_bounds__(256) k_conv(const float* __restrict__ conv_w,
                                              const float* __restrict__ conv_b) {
    __shared__ float2 cw[9 * 64];
    __shared__ float2 cb[64];
    int tid = threadIdx.x;
    for (int i = tid; i < 9 * 64; i += 256) {
        int tap = i >> 6, d2 = i & 63;
        cw[i] = make_float2(conv_w[(2 * d2) * 9 + tap], conv_w[(2 * d2 + 1) * 9 + tap]);
    }
    if (tid < 64) cb[tid] = ((const float2*)conv_b)[tid];
    __syncthreads();
    int idx = blockIdx.x * 256 + tid;
    int d2 = idx & 63;
    int l = idx >> 6;
    int h = l >> 6, w = l & 63;
    float2 acc = cb[d2];
    const float2* xx2 = (const float2*)g_xx;
    #pragma unroll
    for (int kh = -1; kh <= 1; kh++) {
        int hh = h + kh;
        if ((unsigned)hh >= 64u) continue;
        #pragma unroll
        for (int kw = -1; kw <= 1; kw++) {
            int wc = w + kw;
            if ((unsigned)wc >= 64u) continue;
            float2 v = xx2[((hh << 6) | wc) * 64 + d2];
            float2 cc = cw[((kh + 1) * 3 + (kw + 1)) * 64 + d2];
            acc.x = fmaf(cc.x, v.x, acc.x);
            acc.y = fmaf(cc.y, v.y, acc.y);
        }
    }
    acc.x = acc.x / (1.f + __expf(-acc.x));
    acc.y = acc.y / (1.f + __expf(-acc.y));
    ((float2*)g_xcT)[l * 64 + d2] = acc;
}

// ---------------- projection + fused delta ----------------
__global__ void __launch_bounds__(256) k_proj(const float* __restrict__ x_proj_w,
                                              const float* __restrict__ dt_w,
                                              const float* __restrict__ dt_b) {
    __shared__ float xs[32][129];
    __shared__ __align__(16) float Ps[36 * 128];
    __shared__ float dts[4][32];
    __shared__ int sidx[32];
    int k  = blockIdx.y;
    int t0 = blockIdx.x * 32;
    int tid = threadIdx.x;
    if (tid < 32) sidx[tid] = sin_idx(k, t0 + tid);
    __syncthreads();
    for (int i = tid; i < 36 * 128; i += 256)
        Ps[i] = x_proj_w[k * 36 * 128 + i];
    {
        int lane = tid & 31;
        for (int r = tid >> 5; r < 32; r += 8) {
            int s = sidx[r];
            const float4* src = (const float4*)(g_xcT + s * 128);
            float4 v = src[lane];
            xs[r][lane * 4 + 0] = v.x;
            xs[r][lane * 4 + 1] = v.y;
            xs[r][lane * 4 + 2] = v.z;
            xs[r][lane * 4 + 3] = v.w;
        }
    }
    __syncthreads();
    if (tid < 192) {
        int cg = tid >> 4;
        int tg = tid & 15;
        float acc[3][2] = {{0.f,0.f},{0.f,0.f},{0.f,0.f}};
        const float4* Ps4 = (const float4*)Ps;
        const float* r0 = &xs[tg * 2 + 0][0];
        const float* r1 = &xs[tg * 2 + 1][0];
        for (int dd4 = 0; dd4 < 32; dd4++) {
            float4 a0 = Ps4[(cg * 3 + 0) * 32 + dd4];
            float4 a1 = Ps4[(cg * 3 + 1) * 32 + dd4];
            float4 a2 = Ps4[(cg * 3 + 2) * 32 + dd4];
            float b00 = r0[dd4 * 4 + 0], b01 = r0[dd4 * 4 + 1];
            float b02 = r0[dd4 * 4 + 2], b03 = r0[dd4 * 4 + 3];
            float b10 = r1[dd4 * 4 + 0], b11 = r1[dd4 * 4 + 1];
            float b12 = r1[dd4 * 4 + 2], b13 = r1[dd4 * 4 + 3];
            acc[0][0] = fmaf(a0.x, b00, fmaf(a0.y, b01, fmaf(a0.z, b02, fmaf(a0.w, b03, acc[0][0]))));
            acc[0][1] = fmaf(a0.x, b10, fmaf(a0.y, b11, fmaf(a0.z, b12, fmaf(a0.w, b13, acc[0][1]))));
            acc[1][0] = fmaf(a1.x, b00, fmaf(a1.y, b01, fmaf(a1.z, b02, fmaf(a1.w, b03, acc[1][0]))));
            acc[1][1] = fmaf(a1.x, b10, fmaf(a1.y, b11, fmaf(a1.z, b12, fmaf(a1.w, b13, acc[1][1]))));
            acc[2][0] = fmaf(a2.x, b00, fmaf(a2.y, b01, fmaf(a2.z, b02, fmaf(a2.w, b03, acc[2][0]))));
            acc[2][1] = fmaf(a2.x, b10, fmaf(a2.y, b11, fmaf(a2.z, b12, fmaf(a2.w, b13, acc[2][1]))));
        }
        #pragma unroll
        for (int i = 0; i < 3; i++)
            #pragma unroll
            for (int j = 0; j < 2; j++) {
                int c = cg * 3 + i;
                int tl = tg * 2 + j;
                int t = t0 + tl;
                float v = acc[i][j];
                if (c < 4)       dts[c][tl] = v;
                else if (c < 20) g_BC[(size_t)(k * LL + t) * NS + (c - 4)].x = v;
                else             g_BC[(size_t)(k * LL + t) * NS + (c - 20)].y = v;
            }
    }
    __syncthreads();
    {
        int t = tid & 31;
        int w = tid >> 5;
        #pragma unroll
        for (int it = 0; it < 16; it++) {
            int d = w + 8 * it;
            float acc = dt_b[k * 128 + d];
            #pragma unroll
            for (int r = 0; r < 4; r++)
                acc = fmaf(dt_w[(k * 128 + d) * 4 + r], dts[r][t], acc);
            float delta = (acc > 20.f) ? acc : log1pf(__expf(acc));
            float u = xs[t][d];
            g_dd[(size_t)(k * 128 + d) * LL + t0 + t] = make_float2(delta, delta * u);
        }
    }
}

// ---------------- scan pass 1: smem B [t][n], float4 dd (R9 loop, low regs) ----------------
__global__ void __launch_bounds__(512) k_scan1(const float* __restrict__ A_logs) {
    __shared__ float bb[LC * 16];          // 4 KB, [t][n]
    int tid = threadIdx.x;
    int wl = tid >> 5;
    int ln = tid & 31;
    int k = blockIdx.z, chunk = blockIdx.y, xh = blockIdx.x;
    int dp = xh * 16 + wl;
    int half = ln >> 4, n = ln & 15;
    int d = dp + (half << 6);
    int ch = k * 128 + d;
    int tbeg = chunk * LC;

    {
        const float4* src4 = (const float4*)(g_BC + (size_t)(k * LL + tbeg) * NS);
        if (tid < 512) {
            float4 v = src4[tid];
            bb[2 * tid]     = v.x;
            bb[2 * tid + 1] = v.z;
        }
    }
    __syncthreads();

    const float4* pDD4 = (const float4*)(g_dd + (size_t)ch * LL + tbeg);
    float cA = -expf(A_logs[ch * 16 + n]) * 1.44269504f;
    float x = 0.f, sdelta = 0.f;
    #pragma unroll 4
    for (int s2 = 0; s2 < LC / 2; s2++) {
        float4 q = pDD4[s2];
        float b0 = bb[(2 * s2) * 16 + n];
        float b1 = bb[(2 * s2 + 1) * 16 + n];
        float dA;
        asm("ex2.approx.ftz.f32 %0, %1;" : "=f"(dA) : "f"(q.x * cA));
        x = fmaf(dA, x, q.y * b0);
        asm("ex2.approx.ftz.f32 %0, %1;" : "=f"(dA) : "f"(q.z * cA));
        x = fmaf(dA, x, q.w * b1);
        sdelta += q.x + q.z;
    }
    float ap;
    asm("ex2.approx.ftz.f32 %0, %1;" : "=f"(ap) : "f"(sdelta * cA));
    g_chk[((size_t)ch * CHK + chunk) * NS + n] = make_float2(x, ap);
}

// ---------------- scan pass 2: chunk summaries -> initial states ----------------
__global__ void k_scan2() {
    int idx = blockIdx.x * 256 + threadIdx.x;
    if (idx >= NCH * NS) return;
    int ch = idx >> 4;
    int n  = idx & 15;
    float carry = 0.f;
    #pragma unroll 8
    for (int c = 0; c < CHK; c++) {
        size_t off = ((size_t)ch * CHK + c) * NS + n;
        float2 f = g_chk[off];
        g_init[off] = carry;
        carry = fmaf(f.y, carry, f.x);
    }
}

// ---------------- scan pass 3: 512-thread blocks, batched loads, smem y-assembly ----------------
__global__ void __launch_bounds__(512) k_scan3(const float* __restrict__ A_logs) {
    __shared__ __align__(16) float BsmT[16 * 76];
    __shared__ __align__(16) float CsmT[16 * 76];
    __shared__ float xc[16][8][33];        // 16.9 KB
    __shared__ float ytile[8 * 33];
    int tid = threadIdx.x;
    int wl = tid >> 5;                     // 0..15
    int ln = tid & 31;
    int k = blockIdx.z, chunk = blockIdx.y, xh = blockIdx.x;
    int dp = xh * 16 + wl;
    int half = ln >> 4, n = ln & 15;
    int d = dp + (half << 6);
    int ch = k * 128 + d;
    int tbeg = chunk * LC;

    {
        const float2* srcBC = g_BC + (size_t)(k * LL + tbeg) * NS;
        for (int i = tid; i < LC * 16; i += 512) {
            int t = i >> 4, nn = i & 15;
            float2 v = srcBC[i];
            BsmT[nn * 76 + t] = v.x;
            CsmT[nn * 76 + t] = v.y;
        }
    }
    __syncthreads();

    const float4* pDD4 = (const float4*)(g_dd + (size_t)ch * LL + tbeg);
    const float4* pB4 = (const float4*)(BsmT + n * 76);
    const float4* pC4 = (const float4*)(CsmT + n * 76);
    float cA = -expf(A_logs[ch * 16 + n]) * 1.44269504f;
    float x = g_init[((size_t)ch * CHK + chunk) * NS + n];

    int rc = ln >> 4;
    int rj = (ln >> 1) & 7;
    int rh = ln & 1;
    int sr = tid >> 5;         // 0..15 (only 0..7 used for stores)
    int sc = tid & 31;
    int sd = xh * 16 + (sc & 15) + ((sc >> 4) << 6);
    float* ydst0 = g_y + (size_t)(k * LL + tbeg) * 128 + sd;

    for (int t0 = 0; t0 < LC; t0 += 8) {
        // batch the window's loads up front (MLP 4 on dd)
        float4 q0 = pDD4[(t0 >> 1) + 0];
        float4 q1 = pDD4[(t0 >> 1) + 1];
        float4 q2 = pDD4[(t0 >> 1) + 2];
        float4 q3 = pDD4[(t0 >> 1) + 3];
        float4 b40 = pB4[(t0 >> 2) + 0];
        float4 b41 = pB4[(t0 >> 2) + 1];
        float4 c40 = pC4[(t0 >> 2) + 0];
        float4 c41 = pC4[(t0 >> 2) + 1];
        float dA;
        asm("ex2.approx.ftz.f32 %0, %1;" : "=f"(dA) : "f"(q0.x * cA));
        x = fmaf(dA, x, q0.y * b40.x);
        xc[wl][0][ln] = x * c40.x;
        asm("ex2.approx.ftz.f32 %0, %1;" : "=f"(dA) : "f"(q0.z * cA));
        x = fmaf(dA, x, q0.w * b40.y);
        xc[wl][1][ln] = x * c40.y;
        asm("ex2.approx.ftz.f32 %0, %1;" : "=f"(dA) : "f"(q1.x * cA));
        x = fmaf(dA, x, q1.y * b40.z);
        xc[wl][2][ln] = x * c40.z;
        asm("ex2.approx.ftz.f32 %0, %1;" : "=f"(dA) : "f"(q1.z * cA));
        x = fmaf(dA, x, q1.w * b40.w);
        xc[wl][3][ln] = x * c40.w;
        asm("ex2.approx.ftz.f32 %0, %1;" : "=f"(dA) : "f"(q2.x * cA));
        x = fmaf(dA, x, q2.y * b41.x);
        xc[wl][4][ln] = x * c41.x;
        asm("ex2.approx.ftz.f32 %0, %1;" : "=f"(dA) : "f"(q2.z * cA));
        x = fmaf(dA, x, q2.w * b41.y);
        xc[wl][5][ln] = x * c41.y;
        asm("ex2.approx.ftz.f32 %0, %1;" : "=f"(dA) : "f"(q3.x * cA));
        x = fmaf(dA, x, q3.y * b41.z);
        xc[wl][6][ln] = x * c41.z;
        asm("ex2.approx.ftz.f32 %0, %1;" : "=f"(dA) : "f"(q3.z * cA));
        x = fmaf(dA, x, q3.w * b41.w);
        xc[wl][7][ln] = x * c41.w;
        __syncwarp();
        float sum = 0.f;
        #pragma unroll
        for (int m = 0; m < 8; m++)
            sum += xc[wl][rj][rc * 16 + rh * 8 + m];
        sum += __shfl_xor_sync(0xffffffffu, sum, 1);
        if (rh == 0) ytile[rj * 33 + rc * 16 + wl] = sum;
        __syncthreads();
        if (tid < 256) ydst0[(size_t)(t0 + sr) * 128] = ytile[sr * 33 + sc];
        __syncthreads();
    }
}

// ---------------- combine: 4 concurrent positions per block ----------------
__global__ void __launch_bounds__(512) k_comb(const float* __restrict__ Ds,
                                              const float* __restrict__ ln_g,
                                              const float* __restrict__ ln_b,
                                              const float* __restrict__ W_out,
                                              float* __restrict__ out) {
    __shared__ __align__(16) float Wsm[64 * 132];
    __shared__ __align__(16) float gsm[4][132];
    __shared__ float red[4][8];
    __shared__ float mus[4][2];
    __shared__ int ism[6 * 16];
    int tid = threadIdx.x;
    int g = tid >> 7;
    int gt = tid & 127;
    for (int i = tid; i < 64 * 128; i += 512)
        Wsm[(i >> 7) * 132 + (i & 127)] = W_out[i];
    if (tid < 96) {
        int kk = tid >> 4, jj = tid & 15;
        ism[kk * 16 + jj] = iout_idx(kk, blockIdx.x * 16 + jj);
    }
    int d = gt;
    float dsum = 0.f;
    #pragma unroll
    for (int k = 0; k < 5; k++) dsum += Ds[k * 128 + d];
    float d5 = Ds[5 * 128 + d];
    float gg = ln_g[d], bb = ln_b[d];
    int lane = tid & 31;
    int wg = gt >> 5;
    int oo = (wg << 4) + (lane & 15);
    int hh2 = lane >> 4;
    __syncthreads();

    for (int it = 0; it < 4; it++) {
        int jj = it * 4 + g;
        int j = blockIdx.x * 16 + jj;
        float y = 0.f;
        #pragma unroll
        for (int k = 0; k < 6; k++)
            y += g_y[(size_t)(k * LL + ism[k * 16 + jj]) * 128 + d];
        int fl = ((63 - (j >> 6)) << 6) | (j & 63);
        y += dsum * g_xcT[j * 128 + d] + d5 * g_xcT[fl * 128 + d];
        float s1 = y, s2 = y * y;
        #pragma unroll
        for (int o = 16; o; o >>= 1) {
            s1 += __shfl_xor_sync(0xffffffffu, s1, o);
            s2 += __shfl_xor_sync(0xffffffffu, s2, o);
        }
        if (lane == 0) { red[g][wg] = s1; red[g][4 + wg] = s2; }
        __syncthreads();
        if (gt == 0) {
            float S1 = red[g][0] + red[g][1] + red[g][2] + red[g][3];
            float S2 = red[g][4] + red[g][5] + red[g][6] + red[g][7];
            float mu = S1 * (1.f / 128.f);
            float var = S2 * (1.f / 128.f) - mu * mu;
            mus[g][0] = mu;
            mus[g][1] = rsqrtf(var + 1e-5f);
        }
        __syncthreads();
        float yn = (y - mus[g][0]) * mus[g][1] * gg + bb;
        float z = g_z[j * 128 + d];
        gsm[g][d] = yn * (z / (1.f + __expf(-z)));
        __syncthreads();
        {
            float acc = 0.f;
            const float4* wrow = (const float4*)(Wsm + oo * 132 + (hh2 << 6));
            const float4* grow = (const float4*)(gsm[g] + (hh2 << 6));
            #pragma unroll
            for (int q = 0; q < 16; q++) {
                float4 wv = wrow[q];
                float4 gv = grow[q];
                acc = fmaf(wv.x, gv.x, fmaf(wv.y, gv.y, fmaf(wv.z, gv.z, fmaf(wv.w, gv.w, acc))));
            }
            acc += __shfl_xor_sync(0xffffffffu, acc, 16);
            if (hh2 == 0) out[j * 64 + oo] = acc;
        }
        __syncthreads();
    }
}

// ---------------- launch ----------------
extern "C" void kernel_launch(void* const* d_in, const int* in_sizes, int n_in,
                              void* d_out, int out_size) {
    const float* x        = (const float*)d_in[0];
    const float* W_in     = (const float*)d_in[1];
    const float* conv_w   = (const float*)d_in[2];
    const float* conv_b   = (const float*)d_in[3];
    const float* x_proj_w = (const float*)d_in[4];
    const float* dt_w     = (const float*)d_in[5];
    const float* dt_b     = (const float*)d_in[6];
    const float* A_logs   = (const float*)d_in[7];
    const float* Ds       = (const float*)d_in[8];
    const float* ln_g     = (const float*)d_in[9];
    const float* ln_b     = (const float*)d_in[10];
    const float* W_out    = (const float*)d_in[11];
    float* out = (float*)d_out;

    k_inproj<<<128, 256>>>(x, W_in);
    k_conv<<<(LL * 64) / 256, 256>>>(conv_w, conv_b);
    {
        dim3 g(LL / 32, KDIR);
        k_proj<<<g, 256>>>(x_proj_w, dt_w, dt_b);
    }
    {
        dim3 gs(4, CHK, KDIR);
        k_scan1<<<gs, 512>>>(A_logs);
        k_scan2<<<48, 256>>>();
        k_scan3<<<gs, 512>>>(A_logs);
    }
    k_comb<<<256, 512>>>(Ds, ln_g, ln_b, W_out, out);
}